// round 11
// baseline (speedup 1.0000x reference)
#include <cuda_runtime.h>
#include <cuda_fp16.h>
#include <math.h>

#define BATCH 8
#define CW    64
#define H0    256
#define W0    256
#define HP    264
#define WP    264
#define MW    32      // kept kx modes
#define MH    64      // kept ky modes (32 top + 32 bottom)
#define NL    4
#define HW    (HP*WP)            // 69696
#define NPIX  (BATCH*CW*HW)      // 35684352

// ---------------- scratch (device globals; no allocation allowed) ----------
__device__ __align__(128) __half   g_hh[2][NPIX];           // 2 x 71.4 MB
__device__ __align__(128) unsigned g_x1h[BATCH*CW*HP*MW];   // 17.3 MB packed (re,im)
__device__ __align__(128) float    g_x2r[BATCH*CW*128*32];  // 8.4 MB (split re/im rows)
__device__ __align__(128) float2   g_y2[BATCH*CW*MH*MW];    // 8.4 MB
__device__ __align__(128) __half   g_y1h[BATCH*HP*64*64];   // 17.3 MB [b][h][o][kk]
// fp16 fragment tables (k16)
__device__ __align__(128) uint4 g_fwf4[17*4*32];            // W-DFT B frags (nt pairs)
__device__ __align__(128) uint4 g_awf4[4*2*9*32];           // c2r invW B frags (nt pairs)
__device__ __align__(128) uint4 g_fhfh[8*33*32];            // H-DFT A frags
__device__ __align__(128) uint4 g_ghfh[33*8*32];            // invH A frags

__device__ __forceinline__ float gelu_f(float v) {
    return 0.5f * v * (1.0f + erff(v * 0.70710678118654752f));
}

__device__ __forceinline__ unsigned packh(float a, float b) {
    __half2 h = __halves2half2(__float2half_rn(a), __float2half_rn(b));
    return *reinterpret_cast<unsigned*>(&h);
}

// mma.m16n8k16 fp16 in, fp32 accum
__device__ __forceinline__ void mma_f16(float* d, unsigned a0, unsigned a1,
                                        unsigned a2, unsigned a3,
                                        unsigned b0, unsigned b1) {
    asm("mma.sync.aligned.m16n8k16.row.col.f32.f16.f16.f32 "
        "{%0,%1,%2,%3}, {%4,%5,%6,%7}, {%8,%9}, {%0,%1,%2,%3};"
        : "+f"(d[0]), "+f"(d[1]), "+f"(d[2]), "+f"(d[3])
        : "r"(a0), "r"(a1), "r"(a2), "r"(a3), "r"(b0), "r"(b1));
}

__device__ __forceinline__ void ldm_x4(unsigned& d0, unsigned& d1,
                                       unsigned& d2, unsigned& d3, unsigned sa) {
    asm volatile("ldmatrix.sync.aligned.m8n8.x4.shared.b16 {%0,%1,%2,%3}, [%4];"
                 : "=r"(d0), "=r"(d1), "=r"(d2), "=r"(d3) : "r"(sa));
}
__device__ __forceinline__ void ldm_x2(unsigned& d0, unsigned& d1, unsigned sa) {
    asm volatile("ldmatrix.sync.aligned.m8n8.x2.shared.b16 {%0,%1}, [%2];"
                 : "=r"(d0), "=r"(d1) : "r"(sa));
}

#define TWO_PI_D 6.283185307179586476925286766559

__device__ float fwB_val(int n, int w) {
    if (w >= WP) return 0.f;
    int kx = n >> 1, p = n & 1;
    long m = ((long)w * (long)kx) % WP;
    double ang = TWO_PI_D * (double)m / (double)WP;
    double s, c; sincos(ang, &s, &c);
    return p ? (float)(-s) : (float)c;
}
__device__ float awB_val(int kk, int w) {
    if (w >= WP) return 0.f;
    int k = kk >> 1;
    double sc = ((k == 0) ? 1.0 : 2.0) / ((double)HP * (double)WP);
    long m = ((long)k * (long)w) % WP;
    double ang = TWO_PI_D * (double)m / (double)WP;
    double s, c; sincos(ang, &s, &c);
    return (float)((kk & 1) ? (-sc * s) : (sc * c));
}
__device__ float fh_val(int jp, int kp) {
    int j = jp >> 1, pj = jp & 1, h = kp >> 1, ph = kp & 1;
    int ky = (j < 32) ? j : j + (HP - MH);
    long m = ((long)h * (long)ky) % HP;
    double ang = TWO_PI_D * (double)m / (double)HP;
    double s, c; sincos(ang, &s, &c);
    double v = pj ? (ph ? c : -s) : (ph ? s : c);
    return (float)v;
}
__device__ float gh_val(int hpp, int jp) {
    int h = hpp >> 1, ph = hpp & 1, j = jp >> 1, pj = jp & 1;
    int ky = (j < 32) ? j : j + (HP - MH);
    long m = ((long)h * (long)ky) % HP;
    double ang = TWO_PI_D * (double)m / (double)HP;
    double s, c; sincos(ang, &s, &c);
    double v = ph ? (pj ? c : s) : (pj ? -s : c);
    return (float)v;
}

// ---------------- fragment-table init --------------------------------------
__global__ void k_init() {
    int i = blockIdx.x * blockDim.x + threadIdx.x;
    if (i >= 16896) return;
    if (i < 17 * 4 * 32) {   // g_fwf4 [kt][p][lane]: nt pair (2p, 2p+1)
        int kt = i >> 7, rem = i & 127;
        int p = rem >> 5, lane = rem & 31;
        int r = lane >> 2, c = lane & 3;
        int nE = (2 * p) * 8 + r, nO = (2 * p + 1) * 8 + r;
        int w0 = kt * 16 + 2 * c;
        g_fwf4[i] = make_uint4(
            packh(fwB_val(nE, w0),     fwB_val(nE, w0 + 1)),
            packh(fwB_val(nE, w0 + 8), fwB_val(nE, w0 + 9)),
            packh(fwB_val(nO, w0),     fwB_val(nO, w0 + 1)),
            packh(fwB_val(nO, w0 + 8), fwB_val(nO, w0 + 9)));
    }
    if (i < 4 * 2 * 9 * 32) {   // g_awf4 [kt][nh][j2][lane]
        int kt = i / 576, rem = i - kt * 576;
        int nh = rem / 288, rem2 = rem - nh * 288;
        int j2 = rem2 >> 5, lane = rem2 & 31;
        int r = lane >> 2, c = lane & 3;
        int kk0 = kt * 16 + 2 * c;
        int ntA = nh * 17 + ((j2 == 8) ? 16 : 2 * j2);
        int wA = ntA * 8 + r;
        unsigned x = packh(awB_val(kk0, wA),     awB_val(kk0 + 1, wA));
        unsigned y = packh(awB_val(kk0 + 8, wA), awB_val(kk0 + 9, wA));
        unsigned z = 0u, w = 0u;
        if (j2 < 8) {
            int wB = (ntA + 1) * 8 + r;
            z = packh(awB_val(kk0, wB),     awB_val(kk0 + 1, wB));
            w = packh(awB_val(kk0 + 8, wB), awB_val(kk0 + 9, wB));
        }
        g_awf4[i] = make_uint4(x, y, z, w);
    }
    {   // g_fhfh [mt 0..7][kt 0..32][lane]
        int mt = i / (33 * 32);
        if (mt < 8) {
            int rem = i - mt * 33 * 32;
            int kt = rem >> 5, lane = rem & 31;
            int r = lane >> 2, c = lane & 3;
            int row0 = mt * 16 + r, k0 = kt * 16 + 2 * c;
            g_fhfh[i] = make_uint4(
                packh(fh_val(row0, k0),         fh_val(row0, k0 + 1)),
                packh(fh_val(row0 + 8, k0),     fh_val(row0 + 8, k0 + 1)),
                packh(fh_val(row0, k0 + 8),     fh_val(row0, k0 + 9)),
                packh(fh_val(row0 + 8, k0 + 8), fh_val(row0 + 8, k0 + 9)));
        }
    }
    {   // g_ghfh [mt 0..32][kt 0..7][lane]
        int mt = i >> 8;
        if (mt < 33) {
            int rem = i & 255;
            int kt = rem >> 5, lane = rem & 31;
            int r = lane >> 2, c = lane & 3;
            int row0 = mt * 16 + r, k0 = kt * 16 + 2 * c;
            g_ghfh[i] = make_uint4(
                packh(gh_val(row0, k0),         gh_val(row0, k0 + 1)),
                packh(gh_val(row0 + 8, k0),     gh_val(row0 + 8, k0 + 1)),
                packh(gh_val(row0, k0 + 8),     gh_val(row0, k0 + 9)),
                packh(gh_val(row0 + 8, k0 + 8), gh_val(row0 + 8, k0 + 9)));
        }
    }
}

// Zero only the pad region of g_hh[0]
__global__ void k_zero_pad() {
    __half* p = g_hh[0] + (size_t)blockIdx.x * HW;
    int t = threadIdx.x;
    __half z = __float2half_rn(0.f);
    for (int i = t; i < 8 * WP; i += 256)
        p[(H0 + i / WP) * WP + (i % WP)] = z;
    for (int i = t; i < 8 * H0; i += 256)
        p[(i >> 3) * WP + W0 + (i & 7)] = z;
}

// ---------------- lift ------------------------------------------------------
__global__ void k_lift(const float* __restrict__ x,
                       const float* __restrict__ w1, const float* __restrict__ b1,
                       const float* __restrict__ w2, const float* __restrict__ b2) {
    __shared__ float sw1[160], sb1[32], sw2[2048], sb2[64];
    int t = threadIdx.x;
    if (t < 160) sw1[t] = w1[t];
    if (t < 32)  sb1[t] = b1[t];
    for (int i = t; i < 2048; i += 256) sw2[i] = w2[i];
    if (t < 64)  sb2[t] = b2[t];
    __syncthreads();
    int b = blockIdx.x >> 8, h = blockIdx.x & 255, w = t;
    float in5[5];
#pragma unroll
    for (int c = 0; c < 3; ++c)
        in5[c] = x[(((size_t)b * 3 + c) * H0 + h) * W0 + w];
    in5[3] = (float)h * (1.0f / 255.0f);
    in5[4] = (float)w * (1.0f / 255.0f);
    float mid[32];
#pragma unroll
    for (int o = 0; o < 32; ++o) {
        float s = sb1[o];
#pragma unroll
        for (int i = 0; i < 5; ++i) s = fmaf(sw1[o * 5 + i], in5[i], s);
        mid[o] = gelu_f(s);
    }
    __half* hb = g_hh[0];
#pragma unroll 4
    for (int o = 0; o < 64; ++o) {
        float s = sb2[o];
#pragma unroll
        for (int i = 0; i < 32; ++i) s = fmaf(sw2[o * 32 + i], mid[i], s);
        hb[(((size_t)b * CW + o) * HP + h) * WP + w] = __float2half_rn(s);
    }
}

// ---------------- K1: W-DFT via fp16 mma + ldmatrix ------------------------
__global__ __launch_bounds__(256, 3) void k1_wdft(int cur) {
    extern __shared__ unsigned sAw[];                    // (64*132 + 8) words
    const uint4* src = reinterpret_cast<const uint4*>(
        g_hh[cur] + (size_t)blockIdx.x * 64 * WP);
    uint4* dst4 = reinterpret_cast<uint4*>(sAw);
    for (int idx = threadIdx.x; idx < 64 * 33; idx += 256)
        dst4[idx] = src[idx];
    if (threadIdx.x < 8) sAw[64 * 132 + threadIdx.x] = 0u;
    __syncthreads();
    int lane = threadIdx.x & 31, wid = threadIdx.x >> 5;
    int mi = wid & 3, nh = wid >> 2;
    int m0 = mi * 16;
    int c = lane & 3, r = lane >> 2;
    int lrow = lane & 7, q = lane >> 3;
    unsigned abase = (unsigned)__cvta_generic_to_shared(sAw)
                   + ((m0 + ((q & 1) << 3) + lrow) * 132 + ((q >> 1) << 2)) * 4;
    float acc[4][4];
#pragma unroll
    for (int j = 0; j < 4; ++j) {
        acc[j][0] = 0.f; acc[j][1] = 0.f; acc[j][2] = 0.f; acc[j][3] = 0.f;
    }
#pragma unroll 4
    for (int kt = 0; kt < 17; ++kt) {
        unsigned a0, a1, a2, a3;
        ldm_x4(a0, a1, a2, a3, abase + kt * 32);
        uint4 bb0 = __ldg(&g_fwf4[(kt * 4 + nh * 2) * 32 + lane]);
        uint4 bb1 = __ldg(&g_fwf4[(kt * 4 + nh * 2 + 1) * 32 + lane]);
        mma_f16(acc[0], a0, a1, a2, a3, bb0.x, bb0.y);
        mma_f16(acc[1], a0, a1, a2, a3, bb0.z, bb0.w);
        mma_f16(acc[2], a0, a1, a2, a3, bb1.x, bb1.y);
        mma_f16(acc[3], a0, a1, a2, a3, bb1.z, bb1.w);
    }
    size_t row0 = (size_t)blockIdx.x * 64 + m0 + r;
#pragma unroll
    for (int j = 0; j < 4; ++j) {
        int kx = (nh * 4 + j) * 4 + c;
        g_x1h[row0 * MW + kx]       = packh(acc[j][0], acc[j][1]);
        g_x1h[(row0 + 8) * MW + kx] = packh(acc[j][2], acc[j][3]);
    }
}

// ---------------- K2: H-DFT via fp16 mma + ldmatrix ------------------------
// B staged n-major: sBw[n=kx][kword 0..263], stride 268 words
__global__ __launch_bounds__(256, 3) void k2_hdft() {
    extern __shared__ unsigned sBw[];                    // 32*268 = 8576 words
    int bc = blockIdx.x;
    int t = threadIdx.x;
    const unsigned* xp = g_x1h + (size_t)bc * HP * MW;
    for (int idx = t; idx < HP * MW; idx += 256) {
        int h = idx >> 5, kx = idx & 31;
        sBw[kx * 268 + h] = xp[idx];
    }
    __syncthreads();
    int lane = t & 31, wid = t >> 5;                     // wid = mt
    int c = lane & 3, r = lane >> 2;
    int lrow = lane & 7, q = lane >> 3;
    unsigned sbase = (unsigned)__cvta_generic_to_shared(sBw);
    unsigned bb0 = sbase + ((((q < 2) ? 0 : 1) * 8 + lrow) * 268 + ((q & 1) << 2)) * 4;
    unsigned bb1 = sbase + ((((q < 2) ? 2 : 3) * 8 + lrow) * 268 + ((q & 1) << 2)) * 4;
    float acc[4][4];
#pragma unroll
    for (int nt = 0; nt < 4; ++nt) {
        acc[nt][0] = 0.f; acc[nt][1] = 0.f; acc[nt][2] = 0.f; acc[nt][3] = 0.f;
    }
#pragma unroll 3
    for (int kt = 0; kt < 33; ++kt) {
        uint4 fa = __ldg(&g_fhfh[(wid * 33 + kt) * 32 + lane]);
        unsigned b00, b01, b10, b11, b20, b21, b30, b31;
        ldm_x4(b00, b01, b10, b11, bb0 + kt * 32);
        ldm_x4(b20, b21, b30, b31, bb1 + kt * 32);
        mma_f16(acc[0], fa.x, fa.y, fa.z, fa.w, b00, b01);
        mma_f16(acc[1], fa.x, fa.y, fa.z, fa.w, b10, b11);
        mma_f16(acc[2], fa.x, fa.y, fa.z, fa.w, b20, b21);
        mma_f16(acc[3], fa.x, fa.y, fa.z, fa.w, b30, b31);
    }
    int row0 = wid * 16 + r, row1 = row0 + 8;
#pragma unroll
    for (int nt = 0; nt < 4; ++nt) {
        int kxa = nt * 8 + 2 * c;
        *reinterpret_cast<float2*>(&g_x2r[((size_t)bc * 128 + row0) * 32 + kxa]) =
            make_float2(acc[nt][0], acc[nt][1]);
        *reinterpret_cast<float2*>(&g_x2r[((size_t)bc * 128 + row1) * 32 + kxa]) =
            make_float2(acc[nt][2], acc[nt][3]);
    }
}

// ---------------- K3: per-mode channel mixing (x2 -> y2) -------------------
__global__ __launch_bounds__(256) void k3_mix(const float* __restrict__ spw1,
                                              const float* __restrict__ spw2, int l) {
    __shared__ float2 sX[2 * 64 * 32];                   // [b2][i][kx] 32 KB
    int jj = blockIdx.x >> 2, bp = blockIdx.x & 3;
    int b0 = bp * 2;
    int t = threadIdx.x, kx = t & 31, sub = t >> 5;
    for (int idx = t; idx < 4096; idx += 256) {
        int bi = idx >> 11, rest = idx & 2047;
        int i = rest >> 5, kxl = rest & 31;
        const float* pp = g_x2r + ((size_t)((b0 + bi) * CW + i) * 128 + 2 * jj) * 32;
        sX[idx] = make_float2(pp[kxl], pp[32 + kxl]);
    }
    __syncthreads();
    const float2* wp; int jx;
    if (jj < 32) { wp = (const float2*)spw1; jx = jj; }
    else         { wp = (const float2*)spw2; jx = jj - 32; }
    size_t wbase = (size_t)l * 4194304 + (size_t)jx * 32 + kx;
    float2 a0[8], a1[8];
#pragma unroll
    for (int q = 0; q < 8; ++q) { a0[q] = make_float2(0.f, 0.f); a1[q] = make_float2(0.f, 0.f); }
#pragma unroll 2
    for (int i = 0; i < 64; ++i) {
        float2 x0 = sX[i * 32 + kx];
        float2 x1 = sX[2048 + i * 32 + kx];
        size_t row = wbase + (size_t)(i * 64 + sub * 8) * 1024;
#pragma unroll
        for (int q = 0; q < 8; ++q) {
            float2 c = __ldg(&wp[row + (size_t)q * 1024]);
            a0[q].x = fmaf(x0.x, c.x, a0[q].x); a0[q].x = fmaf(-x0.y, c.y, a0[q].x);
            a0[q].y = fmaf(x0.x, c.y, a0[q].y); a0[q].y = fmaf( x0.y, c.x, a0[q].y);
            a1[q].x = fmaf(x1.x, c.x, a1[q].x); a1[q].x = fmaf(-x1.y, c.y, a1[q].x);
            a1[q].y = fmaf(x1.x, c.y, a1[q].y); a1[q].y = fmaf( x1.y, c.x, a1[q].y);
        }
    }
#pragma unroll
    for (int q = 0; q < 8; ++q) {
        int o = sub * 8 + q;
        g_y2[(((size_t)b0       * CW + o) * MH + jj) * MW + kx] = a0[q];
        g_y2[(((size_t)(b0 + 1) * CW + o) * MH + jj) * MW + kx] = a1[q];
    }
}

// ---------------- K4: inverse H-DFT via fp16 mma + ldmatrix ----------------
// B staged n-major: sBw[n=kx][kword 0..63], stride 68 words
__global__ __launch_bounds__(256) void k4_invh() {
    __shared__ unsigned sBw[32 * 68];
    int bo = blockIdx.x, b = bo >> 6, o = bo & 63;
    int t = threadIdx.x;
    const float2* yp = g_y2 + (size_t)bo * MH * MW;
    for (int idx = t; idx < MH * MW; idx += 256) {
        int j = idx >> 5, kx = idx & 31;
        float2 v = yp[idx];
        sBw[kx * 68 + j] = packh(v.x, v.y);
    }
    __syncthreads();
    int lane = t & 31, wid = t >> 5;
    int c = lane & 3, r = lane >> 2;
    int lrow = lane & 7, q = lane >> 3;
    unsigned sbase = (unsigned)__cvta_generic_to_shared(sBw);
    unsigned bb0 = sbase + ((((q < 2) ? 0 : 1) * 8 + lrow) * 68 + ((q & 1) << 2)) * 4;
    unsigned bb1 = sbase + ((((q < 2) ? 2 : 3) * 8 + lrow) * 68 + ((q & 1) << 2)) * 4;
    for (int mt = wid; mt < 33; mt += 8) {
        float acc[4][4];
#pragma unroll
        for (int nt = 0; nt < 4; ++nt) {
            acc[nt][0] = 0.f; acc[nt][1] = 0.f; acc[nt][2] = 0.f; acc[nt][3] = 0.f;
        }
#pragma unroll
        for (int kt = 0; kt < 8; ++kt) {
            uint4 fa = __ldg(&g_ghfh[(mt * 8 + kt) * 32 + lane]);
            unsigned b00, b01, b10, b11, b20, b21, b30, b31;
            ldm_x4(b00, b01, b10, b11, bb0 + kt * 32);
            ldm_x4(b20, b21, b30, b31, bb1 + kt * 32);
            mma_f16(acc[0], fa.x, fa.y, fa.z, fa.w, b00, b01);
            mma_f16(acc[1], fa.x, fa.y, fa.z, fa.w, b10, b11);
            mma_f16(acc[2], fa.x, fa.y, fa.z, fa.w, b20, b21);
            mma_f16(acc[3], fa.x, fa.y, fa.z, fa.w, b30, b31);
        }
        int h0a = mt * 16 + r, h0b = h0a + 8;
        int ha = h0a >> 1, pa = h0a & 1;
        int hb2 = h0b >> 1, pb = h0b & 1;
        size_t basea = ((size_t)(b * HP + ha) * 64 + o) * 64 + pa;
        size_t baseb = ((size_t)(b * HP + hb2) * 64 + o) * 64 + pb;
#pragma unroll
        for (int nt = 0; nt < 4; ++nt) {
            int kka = 2 * (nt * 8 + 2 * c);
            g_y1h[basea + kka]     = __float2half_rn(acc[nt][0]);
            g_y1h[basea + kka + 2] = __float2half_rn(acc[nt][1]);
            g_y1h[baseb + kka]     = __float2half_rn(acc[nt][2]);
            g_y1h[baseb + kka + 2] = __float2half_rn(acc[nt][3]);
        }
    }
}

// ---------------- K5: fp16 mma GEMM + ldmatrix -----------------------------
__global__ __launch_bounds__(256, 2)
void k5_combine(int cur, const float* __restrict__ cw,
                const float* __restrict__ cb, int l,
                float* __restrict__ out) {
    extern __shared__ unsigned s_raw_u[];
    unsigned* sAw = s_raw_u;                      // [o][kpair] stride 68 words
    unsigned* sBw = s_raw_u + 64 * 68;            // n-major [w 0..271][kpair] stride 36
    int bh = blockIdx.x;
    int b = bh / HP, h = bh - b * HP;
    bool last = (l == NL - 1);
    if (last && h >= H0) return;
    int t = threadIdx.x;
    // stage B (conv half, n-major): sBw[w*36 + kp] = (h[2kp][w], h[2kp+1][w])
    {
        const __half* hb = g_hh[cur] + ((size_t)b * CW * HP + h) * WP;
        const size_t rstride = (size_t)HP * WP;
        for (int idx = t; idx < 32 * 66; idx += 256) {
            int kp = idx / 66, cq = idx - kp * 66;
            const unsigned* r0 = reinterpret_cast<const unsigned*>(hb + (size_t)(2 * kp) * rstride);
            const unsigned* r1 = reinterpret_cast<const unsigned*>(hb + (size_t)(2 * kp + 1) * rstride);
            uint2 u0 = *reinterpret_cast<const uint2*>(&r0[cq * 2]);
            uint2 u1 = *reinterpret_cast<const uint2*>(&r1[cq * 2]);
            int w0 = cq * 4;
            sBw[(w0 + 0) * 36 + kp] = __byte_perm(u0.x, u1.x, 0x5410);
            sBw[(w0 + 1) * 36 + kp] = __byte_perm(u0.x, u1.x, 0x7632);
            sBw[(w0 + 2) * 36 + kp] = __byte_perm(u0.y, u1.y, 0x5410);
            sBw[(w0 + 3) * 36 + kp] = __byte_perm(u0.y, u1.y, 0x7632);
        }
        for (int idx = t; idx < 8 * 36; idx += 256)      // pad rows 264..271
            sBw[264 * 36 + idx] = 0u;
    }
    // stage A: conv weights (fp32) + spectral coeffs (fp16 direct)
    {
        const float* cwl = cw + (size_t)l * 4096;
        for (int idx = t; idx < 2048; idx += 256) {
            int o = idx >> 5, ip = idx & 31;
            sAw[o * 68 + ip] = packh(cwl[o * 64 + 2 * ip], cwl[o * 64 + 2 * ip + 1]);
        }
        const unsigned* yb = reinterpret_cast<const unsigned*>(
            g_y1h + (size_t)(b * HP + h) * 4096);
        for (int idx = t; idx < 2048; idx += 256) {
            int o = idx >> 5, kp = idx & 31;
            sAw[o * 68 + 32 + kp] = yb[o * 32 + kp];
        }
    }
    __syncthreads();
    int lane = t & 31, wid = t >> 5;
    int mi = wid & 3, nh = wid >> 2;
    int m0 = mi * 16;
    int c = lane & 3, r = lane >> 2;
    int ntBeg = nh * 17;
    int lrow = lane & 7, q = lane >> 3;
    unsigned abase = (unsigned)__cvta_generic_to_shared(sAw)
                   + ((m0 + ((q & 1) << 3) + lrow) * 68 + ((q >> 1) << 2)) * 4;
    unsigned sbB = (unsigned)__cvta_generic_to_shared(sBw);
    // B ldmatrix base: jp=0 covers nt (ntBeg, ntBeg+1)
    unsigned bjbase = sbB + (((ntBeg + ((q < 2) ? 0 : 1)) * 8 + lrow) * 36 + ((q & 1) << 2)) * 4;
    unsigned b16base = sbB + (((ntBeg + 16) * 8 + ((lane & 15) & 7)) * 36
                               + (((lane >> 3) & 1) << 2)) * 4;
    float acc[17][4];
#pragma unroll
    for (int j = 0; j < 17; ++j) {
        acc[j][0] = 0.f; acc[j][1] = 0.f; acc[j][2] = 0.f; acc[j][3] = 0.f;
    }
    // conv half (kt 0..3): A ldmatrix + B ldmatrix
#pragma unroll
    for (int kt = 0; kt < 4; ++kt) {
        unsigned a0, a1, a2, a3;
        ldm_x4(a0, a1, a2, a3, abase + kt * 32);
#pragma unroll
        for (int jp = 0; jp < 8; ++jp) {
            unsigned b00, b01, b10, b11;
            ldm_x4(b00, b01, b10, b11, bjbase + jp * (16 * 36 * 4) + kt * 32);
            mma_f16(acc[2 * jp],     a0, a1, a2, a3, b00, b01);
            mma_f16(acc[2 * jp + 1], a0, a1, a2, a3, b10, b11);
        }
        unsigned c0, c1;
        ldm_x2(c0, c1, b16base + kt * 32);
        mma_f16(acc[16], a0, a1, a2, a3, c0, c1);
    }
    // spectral half (kt 4..7): A ldmatrix + B frags from g_awf4
#pragma unroll
    for (int kt = 4; kt < 8; ++kt) {
        unsigned a0, a1, a2, a3;
        ldm_x4(a0, a1, a2, a3, abase + kt * 32);
        const uint4* bp = &g_awf4[(((kt - 4) * 2 + nh) * 9) * 32 + lane];
#pragma unroll
        for (int j2 = 0; j2 < 8; ++j2) {
            uint4 bb = __ldg(&bp[j2 * 32]);
            mma_f16(acc[2 * j2],     a0, a1, a2, a3, bb.x, bb.y);
            mma_f16(acc[2 * j2 + 1], a0, a1, a2, a3, bb.z, bb.w);
        }
        uint4 bb = __ldg(&bp[8 * 32]);
        mma_f16(acc[16], a0, a1, a2, a3, bb.x, bb.y);
    }
    int o0 = m0 + r, o1 = o0 + 8;
    float bias0 = __ldg(&cb[l * 64 + o0]);
    float bias1 = __ldg(&cb[l * 64 + o1]);
    __half* hn = g_hh[cur ^ 1];
#pragma unroll
    for (int j = 0; j < 17; ++j) {
        if (nh && j == 16) continue;
        int n0 = (ntBeg + j) * 8;
        int wcol = n0 + 2 * c;
        float2 p0 = make_float2(acc[j][0] + bias0, acc[j][1] + bias0);
        float2 p1 = make_float2(acc[j][2] + bias1, acc[j][3] + bias1);
        if (!last) {
            p0.x = gelu_f(p0.x); p0.y = gelu_f(p0.y);
            p1.x = gelu_f(p1.x); p1.y = gelu_f(p1.y);
            *reinterpret_cast<unsigned*>(
                &hn[(((size_t)b * CW + o0) * HP + h) * WP + wcol]) = packh(p0.x, p0.y);
            *reinterpret_cast<unsigned*>(
                &hn[(((size_t)b * CW + o1) * HP + h) * WP + wcol]) = packh(p1.x, p1.y);
        } else if (n0 < W0) {
            *reinterpret_cast<float2*>(
                &out[(((size_t)b * CW + o0) * H0 + h) * W0 + wcol]) = p0;
            *reinterpret_cast<float2*>(
                &out[(((size_t)b * CW + o1) * H0 + h) * W0 + wcol]) = p1;
        }
    }
}

// ---------------- launch ---------------------------------------------------
extern "C" void kernel_launch(void* const* d_in, const int* in_sizes, int n_in,
                              void* d_out, int out_size) {
    const float* x   = (const float*)d_in[0];
    const float* lw1 = (const float*)d_in[1];
    const float* lb1 = (const float*)d_in[2];
    const float* lw2 = (const float*)d_in[3];
    const float* lb2 = (const float*)d_in[4];
    const float* cw  = (const float*)d_in[5];
    const float* cb  = (const float*)d_in[6];
    const float* sp1 = (const float*)d_in[7];
    const float* sp2 = (const float*)d_in[8];
    float* out = (float*)d_out;

    const int SMEM_K1 = (64 * 132 + 8) * 4;                // 33824
    const int SMEM_K2 = 32 * 268 * 4;                      // 34304
    const int SMEM_K5 = (64 * 68 + 272 * 36) * 4;          // 56576

    cudaFuncSetAttribute(k1_wdft,    cudaFuncAttributeMaxDynamicSharedMemorySize, SMEM_K1);
    cudaFuncSetAttribute(k2_hdft,    cudaFuncAttributeMaxDynamicSharedMemorySize, SMEM_K2);
    cudaFuncSetAttribute(k5_combine, cudaFuncAttributeMaxDynamicSharedMemorySize, SMEM_K5);

    k_init<<<66, 256>>>();
    k_zero_pad<<<BATCH * CW, 256>>>();
    k_lift<<<BATCH * 256, 256>>>(x, lw1, lb1, lw2, lb2);

    for (int l = 0; l < NL; ++l) {
        int cur = l & 1;
        k1_wdft<<<(BATCH * CW * HP) / 64, 256, SMEM_K1>>>(cur);
        k2_hdft<<<BATCH * CW, 256, SMEM_K2>>>();
        k3_mix<<<MH * 4, 256>>>(sp1, sp2, l);
        k4_invh<<<BATCH * CW, 256>>>();
        k5_combine<<<BATCH * HP, 256, SMEM_K5>>>(cur, cw, cb, l, out);
    }
}

// round 13
// speedup vs baseline: 1.0968x; 1.0968x over previous
#include <cuda_runtime.h>
#include <cuda_fp16.h>
#include <math.h>

#define BATCH 8
#define CW    64
#define H0    256
#define W0    256
#define HP    264
#define WP    264
#define MW    32      // kept kx modes
#define MH    64      // kept ky modes (32 top + 32 bottom)
#define NL    4
#define HW    (HP*WP)            // 69696
#define NPIX  (BATCH*CW*HW)      // 35684352

// ---------------- scratch (device globals; no allocation allowed) ----------
__device__ __align__(128) __half   g_hh[2][NPIX];           // 2 x 71.4 MB
__device__ __align__(128) unsigned g_x1h[BATCH*CW*HP*MW];   // 17.3 MB packed (re,im)
__device__ __align__(128) float    g_x2r[BATCH*CW*128*32];  // 8.4 MB (split re/im rows)
__device__ __align__(128) float2   g_y2[BATCH*CW*MH*MW];    // 8.4 MB
__device__ __align__(128) __half   g_y1h[BATCH*HP*64*64];   // 17.3 MB [b][h][o][kk]
// fp16 fragment tables (k16)
__device__ __align__(128) uint2 g_fwfh[17*8*32];            // W-DFT B frags
__device__ __align__(128) uint2 g_awfh[4*34*32];            // c2r invW B frags
__device__ __align__(128) uint4 g_fhfh[8*33*32];            // H-DFT A frags
__device__ __align__(128) uint4 g_ghfh[33*8*32];            // invH A frags

__device__ __forceinline__ float gelu_f(float v) {
    return 0.5f * v * (1.0f + erff(v * 0.70710678118654752f));
}

__device__ __forceinline__ unsigned packh(float a, float b) {
    __half2 h = __halves2half2(__float2half_rn(a), __float2half_rn(b));
    return *reinterpret_cast<unsigned*>(&h);
}

// mma.m16n8k16 fp16 in, fp32 accum
__device__ __forceinline__ void mma_f16(float* d, unsigned a0, unsigned a1,
                                        unsigned a2, unsigned a3,
                                        unsigned b0, unsigned b1) {
    asm("mma.sync.aligned.m16n8k16.row.col.f32.f16.f16.f32 "
        "{%0,%1,%2,%3}, {%4,%5,%6,%7}, {%8,%9}, {%0,%1,%2,%3};"
        : "+f"(d[0]), "+f"(d[1]), "+f"(d[2]), "+f"(d[3])
        : "r"(a0), "r"(a1), "r"(a2), "r"(a3), "r"(b0), "r"(b1));
}

#define TWO_PI_D 6.283185307179586476925286766559

__device__ float fwB_val(int n, int w) {
    if (w >= WP) return 0.f;
    int kx = n >> 1, p = n & 1;
    long m = ((long)w * (long)kx) % WP;
    double ang = TWO_PI_D * (double)m / (double)WP;
    double s, c; sincos(ang, &s, &c);
    return p ? (float)(-s) : (float)c;
}
__device__ float awB_val(int kk, int w) {
    if (w >= WP) return 0.f;
    int k = kk >> 1;
    double sc = ((k == 0) ? 1.0 : 2.0) / ((double)HP * (double)WP);
    long m = ((long)k * (long)w) % WP;
    double ang = TWO_PI_D * (double)m / (double)WP;
    double s, c; sincos(ang, &s, &c);
    return (float)((kk & 1) ? (-sc * s) : (sc * c));
}
__device__ float fh_val(int jp, int kp) {
    int j = jp >> 1, pj = jp & 1, h = kp >> 1, ph = kp & 1;
    int ky = (j < 32) ? j : j + (HP - MH);
    long m = ((long)h * (long)ky) % HP;
    double ang = TWO_PI_D * (double)m / (double)HP;
    double s, c; sincos(ang, &s, &c);
    double v = pj ? (ph ? c : -s) : (ph ? s : c);
    return (float)v;
}
__device__ float gh_val(int hpp, int jp) {
    int h = hpp >> 1, ph = hpp & 1, j = jp >> 1, pj = jp & 1;
    int ky = (j < 32) ? j : j + (HP - MH);
    long m = ((long)h * (long)ky) % HP;
    double ang = TWO_PI_D * (double)m / (double)HP;
    double s, c; sincos(ang, &s, &c);
    double v = ph ? (pj ? c : s) : (pj ? -s : c);
    return (float)v;
}

// ---------------- fragment-table init --------------------------------------
__global__ void k_init() {
    int i = blockIdx.x * blockDim.x + threadIdx.x;
    if (i >= 16896) return;
    if (i < 17 * 8 * 32) {   // g_fwfh [kt][nt][lane]
        int kt = i >> 8, rem = i & 255;
        int nt = rem >> 5, lane = rem & 31;
        int r = lane >> 2, c = lane & 3;
        int n = nt * 8 + r;
        int w0 = kt * 16 + 2 * c;
        g_fwfh[i] = make_uint2(packh(fwB_val(n, w0),     fwB_val(n, w0 + 1)),
                               packh(fwB_val(n, w0 + 8), fwB_val(n, w0 + 9)));
    }
    if (i < 4 * 34 * 32) {   // g_awfh [kt][ntg][lane]
        int kt = i / (34 * 32), rem = i - kt * (34 * 32);
        int ntg = rem >> 5, lane = rem & 31;
        int r = lane >> 2, c = lane & 3;
        int w = ntg * 8 + r;
        int kk0 = kt * 16 + 2 * c;
        g_awfh[i] = make_uint2(packh(awB_val(kk0, w),     awB_val(kk0 + 1, w)),
                               packh(awB_val(kk0 + 8, w), awB_val(kk0 + 9, w)));
    }
    {   // g_fhfh [mt 0..7][kt 0..32][lane]
        int mt = i / (33 * 32);
        if (mt < 8) {
            int rem = i - mt * 33 * 32;
            int kt = rem >> 5, lane = rem & 31;
            int r = lane >> 2, c = lane & 3;
            int row0 = mt * 16 + r, k0 = kt * 16 + 2 * c;
            g_fhfh[i] = make_uint4(
                packh(fh_val(row0, k0),         fh_val(row0, k0 + 1)),
                packh(fh_val(row0 + 8, k0),     fh_val(row0 + 8, k0 + 1)),
                packh(fh_val(row0, k0 + 8),     fh_val(row0, k0 + 9)),
                packh(fh_val(row0 + 8, k0 + 8), fh_val(row0 + 8, k0 + 9)));
        }
    }
    {   // g_ghfh [mt 0..32][kt 0..7][lane]
        int mt = i >> 8;
        if (mt < 33) {
            int rem = i & 255;
            int kt = rem >> 5, lane = rem & 31;
            int r = lane >> 2, c = lane & 3;
            int row0 = mt * 16 + r, k0 = kt * 16 + 2 * c;
            g_ghfh[i] = make_uint4(
                packh(gh_val(row0, k0),         gh_val(row0, k0 + 1)),
                packh(gh_val(row0 + 8, k0),     gh_val(row0 + 8, k0 + 1)),
                packh(gh_val(row0, k0 + 8),     gh_val(row0, k0 + 9)),
                packh(gh_val(row0 + 8, k0 + 8), gh_val(row0 + 8, k0 + 9)));
        }
    }
}

// Zero pad region of g_hh[0] + x1 pad rows (h >= H0) for layer 0
__global__ void k_zero_pad() {
    __half* p = g_hh[0] + (size_t)blockIdx.x * HW;
    int t = threadIdx.x;
    __half z = __float2half_rn(0.f);
    for (int i = t; i < 8 * WP; i += 256)
        p[(H0 + i / WP) * WP + (i % WP)] = z;
    for (int i = t; i < 8 * H0; i += 256)
        p[(i >> 3) * WP + W0 + (i & 7)] = z;
    unsigned* xr = g_x1h + ((size_t)blockIdx.x * HP + H0) * MW;
    for (int i = t; i < 8 * MW; i += 256) xr[i] = 0u;
}

// ---------------- lift (+fused W-DFT for layer 0) --------------------------
__global__ __launch_bounds__(256) void k_lift(
        const float* __restrict__ x,
        const float* __restrict__ w1, const float* __restrict__ b1,
        const float* __restrict__ w2, const float* __restrict__ b2) {
    __shared__ float sw1[160], sb1[32], sw2[2048], sb2[64];
    __shared__ unsigned sT[64 * 132 + 8];                // fp16 tile [o][w-pair]
    int t = threadIdx.x;
    if (t < 160) sw1[t] = w1[t];
    if (t < 32)  sb1[t] = b1[t];
    for (int i = t; i < 2048; i += 256) sw2[i] = w2[i];
    if (t < 64)  sb2[t] = b2[t];
    __syncthreads();
    int b = blockIdx.x >> 8, h = blockIdx.x & 255, w = t;
    float in5[5];
#pragma unroll
    for (int c = 0; c < 3; ++c)
        in5[c] = x[(((size_t)b * 3 + c) * H0 + h) * W0 + w];
    in5[3] = (float)h * (1.0f / 255.0f);
    in5[4] = (float)w * (1.0f / 255.0f);
    float mid[32];
#pragma unroll
    for (int o = 0; o < 32; ++o) {
        float s = sb1[o];
#pragma unroll
        for (int i = 0; i < 5; ++i) s = fmaf(sw1[o * 5 + i], in5[i], s);
        mid[o] = gelu_f(s);
    }
    __half* hb = g_hh[0];
    __half* sTh = reinterpret_cast<__half*>(sT);
#pragma unroll 4
    for (int o = 0; o < 64; ++o) {
        float s = sb2[o];
#pragma unroll
        for (int i = 0; i < 32; ++i) s = fmaf(sw2[o * 32 + i], mid[i], s);
        __half hv = __float2half_rn(s);
        hb[(((size_t)b * CW + o) * HP + h) * WP + w] = hv;
        sTh[o * 264 + w] = hv;
    }
    __half z = __float2half_rn(0.f);
    for (int i = t; i < 64 * 8; i += 256)
        sTh[(i >> 3) * 264 + 256 + (i & 7)] = z;         // pad w 256..263
    if (t < 8) sT[64 * 132 + t] = 0u;
    __syncthreads();
    // fused W-DFT (identical math to standalone k1)
    int lane = t & 31, wid = t >> 5;
    int mi = wid & 3, nh = wid >> 2;
    int m0 = mi * 16;
    int c = lane & 3, r = lane >> 2;
    float acc[4][4];
#pragma unroll
    for (int j = 0; j < 4; ++j) {
        acc[j][0] = 0.f; acc[j][1] = 0.f; acc[j][2] = 0.f; acc[j][3] = 0.f;
    }
    int aw0 = (m0 + r) * 132 + c;
    int aw1 = aw0 + 8 * 132;
#pragma unroll 4
    for (int kt = 0; kt < 17; ++kt) {
        unsigned a0 = sT[aw0 + kt * 8];
        unsigned a1 = sT[aw1 + kt * 8];
        unsigned a2 = sT[aw0 + kt * 8 + 4];
        unsigned a3 = sT[aw1 + kt * 8 + 4];
        const uint2* bp = &g_fwfh[(kt * 8 + nh * 4) * 32 + lane];
#pragma unroll
        for (int j = 0; j < 4; ++j) {
            uint2 bb = __ldg(&bp[j * 32]);
            mma_f16(acc[j], a0, a1, a2, a3, bb.x, bb.y);
        }
    }
    size_t rowc = (size_t)b * CW + m0 + r;
#pragma unroll
    for (int j = 0; j < 4; ++j) {
        int kx = (nh * 4 + j) * 4 + c;
        g_x1h[(rowc * HP + h) * MW + kx]       = packh(acc[j][0], acc[j][1]);
        g_x1h[((rowc + 8) * HP + h) * MW + kx] = packh(acc[j][2], acc[j][3]);
    }
}

// ---------------- K2: H-DFT via fp16 mma -----------------------------------
// per (b,c): C[128 j'][32 kx] = A[128][528] x B[528][32]; A const (g_fhfh)
__global__ __launch_bounds__(256, 3) void k2_hdft() {
    extern __shared__ unsigned sBw[];                    // 264*40 words
    int bc = blockIdx.x;
    int t = threadIdx.x;
    const uint4* xp = reinterpret_cast<const uint4*>(g_x1h + (size_t)bc * HP * MW);
    for (int idx = t; idx < HP * 8; idx += 256) {
        int h = idx >> 3, kq = idx & 7;
        *reinterpret_cast<uint4*>(&sBw[h * 40 + kq * 4]) = xp[idx];
    }
    __syncthreads();
    int lane = t & 31, wid = t >> 5;                     // wid = mt
    int c = lane & 3, r = lane >> 2;
    float acc[4][4];
#pragma unroll
    for (int nt = 0; nt < 4; ++nt) {
        acc[nt][0] = 0.f; acc[nt][1] = 0.f; acc[nt][2] = 0.f; acc[nt][3] = 0.f;
    }
#pragma unroll 3
    for (int kt = 0; kt < 33; ++kt) {
        uint4 fa = __ldg(&g_fhfh[(wid * 33 + kt) * 32 + lane]);
        int bw = (kt * 8 + c) * 40 + r;
#pragma unroll
        for (int nt = 0; nt < 4; ++nt) {
            unsigned b0 = sBw[bw + nt * 8];
            unsigned b1 = sBw[bw + 4 * 40 + nt * 8];
            mma_f16(acc[nt], fa.x, fa.y, fa.z, fa.w, b0, b1);
        }
    }
    int row0 = wid * 16 + r, row1 = row0 + 8;
#pragma unroll
    for (int nt = 0; nt < 4; ++nt) {
        int kxa = nt * 8 + 2 * c;
        *reinterpret_cast<float2*>(&g_x2r[((size_t)bc * 128 + row0) * 32 + kxa]) =
            make_float2(acc[nt][0], acc[nt][1]);
        *reinterpret_cast<float2*>(&g_x2r[((size_t)bc * 128 + row1) * 32 + kxa]) =
            make_float2(acc[nt][2], acc[nt][3]);
    }
}

// ---------------- K3: per-mode channel mixing (x2 -> y2) -------------------
__global__ __launch_bounds__(256) void k3_mix(const float* __restrict__ spw1,
                                              const float* __restrict__ spw2, int l) {
    __shared__ float2 sX[2 * 64 * 32];                   // [b2][i][kx] 32 KB
    int jj = blockIdx.x >> 2, bp = blockIdx.x & 3;
    int b0 = bp * 2;
    int t = threadIdx.x, kx = t & 31, sub = t >> 5;
    for (int idx = t; idx < 4096; idx += 256) {
        int bi = idx >> 11, rest = idx & 2047;
        int i = rest >> 5, kxl = rest & 31;
        const float* pp = g_x2r + ((size_t)((b0 + bi) * CW + i) * 128 + 2 * jj) * 32;
        sX[idx] = make_float2(pp[kxl], pp[32 + kxl]);
    }
    __syncthreads();
    const float2* wp; int jx;
    if (jj < 32) { wp = (const float2*)spw1; jx = jj; }
    else         { wp = (const float2*)spw2; jx = jj - 32; }
    size_t wbase = (size_t)l * 4194304 + (size_t)jx * 32 + kx;
    float2 a0[8], a1[8];
#pragma unroll
    for (int q = 0; q < 8; ++q) { a0[q] = make_float2(0.f, 0.f); a1[q] = make_float2(0.f, 0.f); }
#pragma unroll 2
    for (int i = 0; i < 64; ++i) {
        float2 x0 = sX[i * 32 + kx];
        float2 x1 = sX[2048 + i * 32 + kx];
        size_t row = wbase + (size_t)(i * 64 + sub * 8) * 1024;
#pragma unroll
        for (int q = 0; q < 8; ++q) {
            float2 c = __ldg(&wp[row + (size_t)q * 1024]);
            a0[q].x = fmaf(x0.x, c.x, a0[q].x); a0[q].x = fmaf(-x0.y, c.y, a0[q].x);
            a0[q].y = fmaf(x0.x, c.y, a0[q].y); a0[q].y = fmaf( x0.y, c.x, a0[q].y);
            a1[q].x = fmaf(x1.x, c.x, a1[q].x); a1[q].x = fmaf(-x1.y, c.y, a1[q].x);
            a1[q].y = fmaf(x1.x, c.y, a1[q].y); a1[q].y = fmaf( x1.y, c.x, a1[q].y);
        }
    }
#pragma unroll
    for (int q = 0; q < 8; ++q) {
        int o = sub * 8 + q;
        g_y2[(((size_t)b0       * CW + o) * MH + jj) * MW + kx] = a0[q];
        g_y2[(((size_t)(b0 + 1) * CW + o) * MH + jj) * MW + kx] = a1[q];
    }
}

// ---------------- K4: inverse H-DFT via fp16 mma ---------------------------
// per (b,o): C[528 h'][32 kx] = A[528][128] x B[128][32]; A const (g_ghfh)
__global__ __launch_bounds__(256) void k4_invh() {
    __shared__ unsigned sBw[64 * 40];
    int bo = blockIdx.x, b = bo >> 6, o = bo & 63;
    int t = threadIdx.x;
    const float2* yp = g_y2 + (size_t)bo * MH * MW;
    for (int idx = t; idx < MH * MW; idx += 256) {
        int j = idx >> 5, kx = idx & 31;
        float2 v = yp[idx];
        sBw[j * 40 + kx] = packh(v.x, v.y);
    }
    __syncthreads();
    int lane = t & 31, wid = t >> 5;
    int c = lane & 3, r = lane >> 2;
    for (int mt = wid; mt < 33; mt += 8) {
        float acc[4][4];
#pragma unroll
        for (int nt = 0; nt < 4; ++nt) {
            acc[nt][0] = 0.f; acc[nt][1] = 0.f; acc[nt][2] = 0.f; acc[nt][3] = 0.f;
        }
#pragma unroll
        for (int kt = 0; kt < 8; ++kt) {
            uint4 fa = __ldg(&g_ghfh[(mt * 8 + kt) * 32 + lane]);
            int bw = (kt * 8 + c) * 40 + r;
#pragma unroll
            for (int nt = 0; nt < 4; ++nt) {
                unsigned b0 = sBw[bw + nt * 8];
                unsigned b1 = sBw[bw + 4 * 40 + nt * 8];
                mma_f16(acc[nt], fa.x, fa.y, fa.z, fa.w, b0, b1);
            }
        }
        int h0a = mt * 16 + r, h0b = h0a + 8;
        int ha = h0a >> 1, pa = h0a & 1;
        int hb2 = h0b >> 1, pb = h0b & 1;
        size_t basea = ((size_t)(b * HP + ha) * 64 + o) * 64 + pa;
        size_t baseb = ((size_t)(b * HP + hb2) * 64 + o) * 64 + pb;
#pragma unroll
        for (int nt = 0; nt < 4; ++nt) {
            int kka = 2 * (nt * 8 + 2 * c);
            g_y1h[basea + kka]     = __float2half_rn(acc[nt][0]);
            g_y1h[basea + kka + 2] = __float2half_rn(acc[nt][1]);
            g_y1h[baseb + kka]     = __float2half_rn(acc[nt][2]);
            g_y1h[baseb + kka + 2] = __float2half_rn(acc[nt][3]);
        }
    }
}

// ---------------- K5: fp16 mma GEMM + fused W-DFT of the output ------------
__global__ __launch_bounds__(256, 2)
void k5_combine(int cur, const float* __restrict__ cw,
                const float* __restrict__ cb, int l,
                float* __restrict__ out) {
    extern __shared__ unsigned s_raw_u[];
    unsigned* sAw = s_raw_u;                      // [o][kpair] stride 68 words
    unsigned* sBw = s_raw_u + 64 * 68;            // [kpair][w] stride 264 (+16 slack)
    unsigned* sT  = s_raw_u + 64 * 68 + 32 * 264 + 16;  // out tile [o][w-pair] 64*132+8
    int bh = blockIdx.x;
    int b = bh / HP, h = bh - b * HP;
    bool last = (l == NL - 1);
    if (last && h >= H0) return;
    int t = threadIdx.x;
    // stage B (conv half k<64): channel pairs (2kp, 2kp+1), fp16 source
    {
        const __half* hb = g_hh[cur] + ((size_t)b * CW * HP + h) * WP;
        const size_t rstride = (size_t)HP * WP;
        for (int idx = t; idx < 32 * 66; idx += 256) {
            int kp = idx / 66, cq = idx - kp * 66;
            const unsigned* r0 = reinterpret_cast<const unsigned*>(hb + (size_t)(2 * kp) * rstride);
            const unsigned* r1 = reinterpret_cast<const unsigned*>(hb + (size_t)(2 * kp + 1) * rstride);
            uint2 u0 = *reinterpret_cast<const uint2*>(&r0[cq * 2]);
            uint2 u1 = *reinterpret_cast<const uint2*>(&r1[cq * 2]);
            int wb = kp * 264 + cq * 4;
            sBw[wb]     = __byte_perm(u0.x, u1.x, 0x5410);
            sBw[wb + 1] = __byte_perm(u0.x, u1.x, 0x7632);
            sBw[wb + 2] = __byte_perm(u0.y, u1.y, 0x5410);
            sBw[wb + 3] = __byte_perm(u0.y, u1.y, 0x7632);
        }
        if (t < 16) sBw[32 * 264 + t] = 0u;
    }
    // stage A: conv weights (fp32 src) + spectral coeffs (fp16 src, direct copy)
    {
        const float* cwl = cw + (size_t)l * 4096;
        for (int idx = t; idx < 2048; idx += 256) {
            int o = idx >> 5, ip = idx & 31;
            sAw[o * 68 + ip] = packh(cwl[o * 64 + 2 * ip], cwl[o * 64 + 2 * ip + 1]);
        }
        const unsigned* yb = reinterpret_cast<const unsigned*>(
            g_y1h + (size_t)(b * HP + h) * 4096);
        for (int idx = t; idx < 2048; idx += 256) {
            int o = idx >> 5, kp = idx & 31;
            sAw[o * 68 + 32 + kp] = yb[o * 32 + kp];
        }
    }
    __syncthreads();
    int lane = t & 31, wid = t >> 5;
    int mi = wid & 3, nh = wid >> 2;
    int m0 = mi * 16;
    int c = lane & 3, r = lane >> 2;
    int ntBeg = nh * 17;
    float acc[17][4];
#pragma unroll
    for (int j = 0; j < 17; ++j) {
        acc[j][0] = 0.f; acc[j][1] = 0.f; acc[j][2] = 0.f; acc[j][3] = 0.f;
    }
    int aw0 = (m0 + r) * 68 + c;
    int aw1 = aw0 + 8 * 68;
    // conv half (kt 0..3): B from smem
#pragma unroll
    for (int kt = 0; kt < 4; ++kt) {
        unsigned a0 = sAw[aw0 + kt * 8];
        unsigned a1 = sAw[aw1 + kt * 8];
        unsigned a2 = sAw[aw0 + kt * 8 + 4];
        unsigned a3 = sAw[aw1 + kt * 8 + 4];
        int bw = (kt * 8 + c) * 264 + r + ntBeg * 8;
#pragma unroll
        for (int j = 0; j < 17; ++j) {
            unsigned b0 = sBw[bw + j * 8];
            unsigned b1 = sBw[bw + 4 * 264 + j * 8];
            mma_f16(acc[j], a0, a1, a2, a3, b0, b1);
        }
    }
    // spectral half (kt 4..7): B frags pre-swizzled in g_awfh
#pragma unroll
    for (int kt = 4; kt < 8; ++kt) {
        unsigned a0 = sAw[aw0 + kt * 8];
        unsigned a1 = sAw[aw1 + kt * 8];
        unsigned a2 = sAw[aw0 + kt * 8 + 4];
        unsigned a3 = sAw[aw1 + kt * 8 + 4];
        const uint2* bp = &g_awfh[((kt - 4) * 34 + ntBeg) * 32 + lane];
#pragma unroll
        for (int j = 0; j < 17; ++j) {
            uint2 bb = __ldg(&bp[j * 32]);
            mma_f16(acc[j], a0, a1, a2, a3, bb.x, bb.y);
        }
    }
    int o0 = m0 + r, o1 = o0 + 8;
    float bias0 = __ldg(&cb[l * 64 + o0]);
    float bias1 = __ldg(&cb[l * 64 + o1]);
    __half* hn = g_hh[cur ^ 1];
#pragma unroll
    for (int j = 0; j < 17; ++j) {
        if (nh && j == 16) continue;
        int n0 = (ntBeg + j) * 8;
        int wcol = n0 + 2 * c;
        float2 p0 = make_float2(acc[j][0] + bias0, acc[j][1] + bias0);
        float2 p1 = make_float2(acc[j][2] + bias1, acc[j][3] + bias1);
        if (!last) {
            p0.x = gelu_f(p0.x); p0.y = gelu_f(p0.y);
            p1.x = gelu_f(p1.x); p1.y = gelu_f(p1.y);
            unsigned u0 = packh(p0.x, p0.y);
            unsigned u1 = packh(p1.x, p1.y);
            *reinterpret_cast<unsigned*>(
                &hn[(((size_t)b * CW + o0) * HP + h) * WP + wcol]) = u0;
            *reinterpret_cast<unsigned*>(
                &hn[(((size_t)b * CW + o1) * HP + h) * WP + wcol]) = u1;
            int wword = 4 * (ntBeg + j) + c;
            sT[o0 * 132 + wword] = u0;
            sT[o1 * 132 + wword] = u1;
        } else if (n0 < W0) {
            *reinterpret_cast<float2*>(
                &out[(((size_t)b * CW + o0) * H0 + h) * W0 + wcol]) = p0;
            *reinterpret_cast<float2*>(
                &out[(((size_t)b * CW + o1) * H0 + h) * W0 + wcol]) = p1;
        }
    }
    if (!last) {
        if (t < 8) sT[64 * 132 + t] = 0u;
        __syncthreads();
        // fused W-DFT of the freshly computed field row-block (next layer's x1)
        float fac[4][4];
#pragma unroll
        for (int j = 0; j < 4; ++j) {
            fac[j][0] = 0.f; fac[j][1] = 0.f; fac[j][2] = 0.f; fac[j][3] = 0.f;
        }
        int fa0 = (m0 + r) * 132 + c;
        int fa1 = fa0 + 8 * 132;
#pragma unroll 4
        for (int kt = 0; kt < 17; ++kt) {
            unsigned a0 = sT[fa0 + kt * 8];
            unsigned a1 = sT[fa1 + kt * 8];
            unsigned a2 = sT[fa0 + kt * 8 + 4];
            unsigned a3 = sT[fa1 + kt * 8 + 4];
            const uint2* bp = &g_fwfh[(kt * 8 + nh * 4) * 32 + lane];
#pragma unroll
            for (int j = 0; j < 4; ++j) {
                uint2 bb = __ldg(&bp[j * 32]);
                mma_f16(fac[j], a0, a1, a2, a3, bb.x, bb.y);
            }
        }
        size_t rowc = (size_t)b * CW + m0 + r;
#pragma unroll
        for (int j = 0; j < 4; ++j) {
            int kx = (nh * 4 + j) * 4 + c;
            g_x1h[(rowc * HP + h) * MW + kx]       = packh(fac[j][0], fac[j][1]);
            g_x1h[((rowc + 8) * HP + h) * MW + kx] = packh(fac[j][2], fac[j][3]);
        }
    }
}

// ---------------- launch ---------------------------------------------------
extern "C" void kernel_launch(void* const* d_in, const int* in_sizes, int n_in,
                              void* d_out, int out_size) {
    const float* x   = (const float*)d_in[0];
    const float* lw1 = (const float*)d_in[1];
    const float* lb1 = (const float*)d_in[2];
    const float* lw2 = (const float*)d_in[3];
    const float* lb2 = (const float*)d_in[4];
    const float* cw  = (const float*)d_in[5];
    const float* cb  = (const float*)d_in[6];
    const float* sp1 = (const float*)d_in[7];
    const float* sp2 = (const float*)d_in[8];
    float* out = (float*)d_out;

    const int SMEM_K2 = 264 * 40 * 4;                              // 42240
    const int SMEM_K5 = (64 * 68 + 32 * 264 + 16 + 64 * 132 + 8) * 4;  // 85088

    cudaFuncSetAttribute(k2_hdft,    cudaFuncAttributeMaxDynamicSharedMemorySize, SMEM_K2);
    cudaFuncSetAttribute(k5_combine, cudaFuncAttributeMaxDynamicSharedMemorySize, SMEM_K5);

    k_init<<<66, 256>>>();
    k_zero_pad<<<BATCH * CW, 256>>>();
    k_lift<<<BATCH * 256, 256>>>(x, lw1, lb1, lw2, lb2);

    for (int l = 0; l < NL; ++l) {
        int cur = l & 1;
        k2_hdft<<<BATCH * CW, 256, SMEM_K2>>>();
        k3_mix<<<MH * 4, 256>>>(sp1, sp2, l);
        k4_invh<<<BATCH * CW, 256>>>();
        k5_combine<<<BATCH * HP, 256, SMEM_K5>>>(cur, cw, cb, l, out);
    }
}

// round 14
// speedup vs baseline: 1.1283x; 1.0287x over previous
#include <cuda_runtime.h>
#include <cuda_fp16.h>
#include <math.h>

#define BATCH 8
#define CW    64
#define H0    256
#define W0    256
#define HP    264
#define WP    264
#define MW    32      // kept kx modes
#define MH    64      // kept ky modes (32 top + 32 bottom)
#define NL    4
#define HW    (HP*WP)            // 69696
#define NPIX  (BATCH*CW*HW)      // 35684352

// ---------------- scratch (device globals; no allocation allowed) ----------
__device__ __align__(128) __half   g_hh[2][NPIX];           // 2 x 71.4 MB
__device__ __align__(128) unsigned g_x1h[BATCH*CW*HP*MW];   // 17.3 MB packed (re,im)
__device__ __align__(128) float    g_x2r[BATCH*CW*128*32];  // 8.4 MB (split re/im rows)
__device__ __align__(128) float2   g_y2[BATCH*CW*MH*MW];    // 8.4 MB
__device__ __align__(128) __half   g_y1h[BATCH*HP*64*64];   // 17.3 MB [b][h][o][kk]
// fp16 fragment tables (k16)
__device__ __align__(128) uint2 g_fwfh[17*8*32];            // W-DFT B frags
__device__ __align__(128) uint2 g_awfh[4*34*32];            // c2r invW B frags
__device__ __align__(128) uint4 g_fhfh[8*33*32];            // H-DFT A frags
__device__ __align__(128) uint4 g_ghfh[33*8*32];            // invH A frags

__device__ __forceinline__ float gelu_f(float v) {
    return 0.5f * v * (1.0f + erff(v * 0.70710678118654752f));
}

__device__ __forceinline__ unsigned packh(float a, float b) {
    __half2 h = __halves2half2(__float2half_rn(a), __float2half_rn(b));
    return *reinterpret_cast<unsigned*>(&h);
}

// mma.m16n8k16 fp16 in, fp32 accum
__device__ __forceinline__ void mma_f16(float* d, unsigned a0, unsigned a1,
                                        unsigned a2, unsigned a3,
                                        unsigned b0, unsigned b1) {
    asm("mma.sync.aligned.m16n8k16.row.col.f32.f16.f16.f32 "
        "{%0,%1,%2,%3}, {%4,%5,%6,%7}, {%8,%9}, {%0,%1,%2,%3};"
        : "+f"(d[0]), "+f"(d[1]), "+f"(d[2]), "+f"(d[3])
        : "r"(a0), "r"(a1), "r"(a2), "r"(a3), "r"(b0), "r"(b1));
}

#define TWO_PI_D 6.283185307179586476925286766559

__device__ float fwB_val(int n, int w) {
    if (w >= WP) return 0.f;
    int kx = n >> 1, p = n & 1;
    long m = ((long)w * (long)kx) % WP;
    double ang = TWO_PI_D * (double)m / (double)WP;
    double s, c; sincos(ang, &s, &c);
    return p ? (float)(-s) : (float)c;
}
__device__ float awB_val(int kk, int w) {
    if (w >= WP) return 0.f;
    int k = kk >> 1;
    double sc = ((k == 0) ? 1.0 : 2.0) / ((double)HP * (double)WP);
    long m = ((long)k * (long)w) % WP;
    double ang = TWO_PI_D * (double)m / (double)WP;
    double s, c; sincos(ang, &s, &c);
    return (float)((kk & 1) ? (-sc * s) : (sc * c));
}
__device__ float fh_val(int jp, int kp) {
    int j = jp >> 1, pj = jp & 1, h = kp >> 1, ph = kp & 1;
    int ky = (j < 32) ? j : j + (HP - MH);
    long m = ((long)h * (long)ky) % HP;
    double ang = TWO_PI_D * (double)m / (double)HP;
    double s, c; sincos(ang, &s, &c);
    double v = pj ? (ph ? c : -s) : (ph ? s : c);
    return (float)v;
}
__device__ float gh_val(int hpp, int jp) {
    int h = hpp >> 1, ph = hpp & 1, j = jp >> 1, pj = jp & 1;
    int ky = (j < 32) ? j : j + (HP - MH);
    long m = ((long)h * (long)ky) % HP;
    double ang = TWO_PI_D * (double)m / (double)HP;
    double s, c; sincos(ang, &s, &c);
    double v = ph ? (pj ? c : s) : (pj ? -s : c);
    return (float)v;
}

// ---------------- fragment-table init --------------------------------------
__global__ void k_init() {
    int i = blockIdx.x * blockDim.x + threadIdx.x;
    if (i >= 16896) return;
    if (i < 17 * 8 * 32) {   // g_fwfh [kt][nt][lane]
        int kt = i >> 8, rem = i & 255;
        int nt = rem >> 5, lane = rem & 31;
        int r = lane >> 2, c = lane & 3;
        int n = nt * 8 + r;
        int w0 = kt * 16 + 2 * c;
        g_fwfh[i] = make_uint2(packh(fwB_val(n, w0),     fwB_val(n, w0 + 1)),
                               packh(fwB_val(n, w0 + 8), fwB_val(n, w0 + 9)));
    }
    if (i < 4 * 34 * 32) {   // g_awfh [kt][ntg][lane]
        int kt = i / (34 * 32), rem = i - kt * (34 * 32);
        int ntg = rem >> 5, lane = rem & 31;
        int r = lane >> 2, c = lane & 3;
        int w = ntg * 8 + r;
        int kk0 = kt * 16 + 2 * c;
        g_awfh[i] = make_uint2(packh(awB_val(kk0, w),     awB_val(kk0 + 1, w)),
                               packh(awB_val(kk0 + 8, w), awB_val(kk0 + 9, w)));
    }
    {   // g_fhfh [mt 0..7][kt 0..32][lane]
        int mt = i / (33 * 32);
        if (mt < 8) {
            int rem = i - mt * 33 * 32;
            int kt = rem >> 5, lane = rem & 31;
            int r = lane >> 2, c = lane & 3;
            int row0 = mt * 16 + r, k0 = kt * 16 + 2 * c;
            g_fhfh[i] = make_uint4(
                packh(fh_val(row0, k0),         fh_val(row0, k0 + 1)),
                packh(fh_val(row0 + 8, k0),     fh_val(row0 + 8, k0 + 1)),
                packh(fh_val(row0, k0 + 8),     fh_val(row0, k0 + 9)),
                packh(fh_val(row0 + 8, k0 + 8), fh_val(row0 + 8, k0 + 9)));
        }
    }
    {   // g_ghfh [mt 0..32][kt 0..7][lane]
        int mt = i >> 8;
        if (mt < 33) {
            int rem = i & 255;
            int kt = rem >> 5, lane = rem & 31;
            int r = lane >> 2, c = lane & 3;
            int row0 = mt * 16 + r, k0 = kt * 16 + 2 * c;
            g_ghfh[i] = make_uint4(
                packh(gh_val(row0, k0),         gh_val(row0, k0 + 1)),
                packh(gh_val(row0 + 8, k0),     gh_val(row0 + 8, k0 + 1)),
                packh(gh_val(row0, k0 + 8),     gh_val(row0, k0 + 9)),
                packh(gh_val(row0 + 8, k0 + 8), gh_val(row0 + 8, k0 + 9)));
        }
    }
}

// Zero pad region of g_hh[0] + x1 pad rows (h >= H0) for layer 0
__global__ void k_zero_pad() {
    __half* p = g_hh[0] + (size_t)blockIdx.x * HW;
    int t = threadIdx.x;
    __half z = __float2half_rn(0.f);
    for (int i = t; i < 8 * WP; i += 256)
        p[(H0 + i / WP) * WP + (i % WP)] = z;
    for (int i = t; i < 8 * H0; i += 256)
        p[(i >> 3) * WP + W0 + (i & 7)] = z;
    unsigned* xr = g_x1h + ((size_t)blockIdx.x * HP + H0) * MW;
    for (int i = t; i < 8 * MW; i += 256) xr[i] = 0u;
}

// ---------------- lift (+fused W-DFT for layer 0) --------------------------
__global__ __launch_bounds__(256) void k_lift(
        const float* __restrict__ x,
        const float* __restrict__ w1, const float* __restrict__ b1,
        const float* __restrict__ w2, const float* __restrict__ b2) {
    __shared__ float sw1[160], sb1[32], sw2[2048], sb2[64];
    __shared__ unsigned sT[64 * 132 + 8];                // fp16 tile [o][w-pair]
    int t = threadIdx.x;
    if (t < 160) sw1[t] = w1[t];
    if (t < 32)  sb1[t] = b1[t];
    for (int i = t; i < 2048; i += 256) sw2[i] = w2[i];
    if (t < 64)  sb2[t] = b2[t];
    __syncthreads();
    int b = blockIdx.x >> 8, h = blockIdx.x & 255, w = t;
    float in5[5];
#pragma unroll
    for (int c = 0; c < 3; ++c)
        in5[c] = x[(((size_t)b * 3 + c) * H0 + h) * W0 + w];
    in5[3] = (float)h * (1.0f / 255.0f);
    in5[4] = (float)w * (1.0f / 255.0f);
    float mid[32];
#pragma unroll
    for (int o = 0; o < 32; ++o) {
        float s = sb1[o];
#pragma unroll
        for (int i = 0; i < 5; ++i) s = fmaf(sw1[o * 5 + i], in5[i], s);
        mid[o] = gelu_f(s);
    }
    __half* hb = g_hh[0];
    __half* sTh = reinterpret_cast<__half*>(sT);
#pragma unroll 4
    for (int o = 0; o < 64; ++o) {
        float s = sb2[o];
#pragma unroll
        for (int i = 0; i < 32; ++i) s = fmaf(sw2[o * 32 + i], mid[i], s);
        __half hv = __float2half_rn(s);
        hb[(((size_t)b * CW + o) * HP + h) * WP + w] = hv;
        sTh[o * 264 + w] = hv;
    }
    __half z = __float2half_rn(0.f);
    for (int i = t; i < 64 * 8; i += 256)
        sTh[(i >> 3) * 264 + 256 + (i & 7)] = z;         // pad w 256..263
    if (t < 8) sT[64 * 132 + t] = 0u;
    __syncthreads();
    // fused W-DFT (identical math to standalone k1)
    int lane = t & 31, wid = t >> 5;
    int mi = wid & 3, nh = wid >> 2;
    int m0 = mi * 16;
    int c = lane & 3, r = lane >> 2;
    float acc[4][4];
#pragma unroll
    for (int j = 0; j < 4; ++j) {
        acc[j][0] = 0.f; acc[j][1] = 0.f; acc[j][2] = 0.f; acc[j][3] = 0.f;
    }
    int aw0 = (m0 + r) * 132 + c;
    int aw1 = aw0 + 8 * 132;
#pragma unroll 4
    for (int kt = 0; kt < 17; ++kt) {
        unsigned a0 = sT[aw0 + kt * 8];
        unsigned a1 = sT[aw1 + kt * 8];
        unsigned a2 = sT[aw0 + kt * 8 + 4];
        unsigned a3 = sT[aw1 + kt * 8 + 4];
        const uint2* bp = &g_fwfh[(kt * 8 + nh * 4) * 32 + lane];
#pragma unroll
        for (int j = 0; j < 4; ++j) {
            uint2 bb = __ldg(&bp[j * 32]);
            mma_f16(acc[j], a0, a1, a2, a3, bb.x, bb.y);
        }
    }
    size_t rowc = (size_t)b * CW + m0 + r;
#pragma unroll
    for (int j = 0; j < 4; ++j) {
        int kx = (nh * 4 + j) * 4 + c;
        g_x1h[(rowc * HP + h) * MW + kx]       = packh(acc[j][0], acc[j][1]);
        g_x1h[((rowc + 8) * HP + h) * MW + kx] = packh(acc[j][2], acc[j][3]);
    }
}

// ---------------- K2: H-DFT via fp16 mma -----------------------------------
// per (b,c): C[128 j'][32 kx] = A[128][528] x B[528][32]; A const (g_fhfh)
__global__ __launch_bounds__(256, 4) void k2_hdft() {
    extern __shared__ unsigned sBw[];                    // 264*40 words
    int bc = blockIdx.x;
    int t = threadIdx.x;
    const uint4* xp = reinterpret_cast<const uint4*>(g_x1h + (size_t)bc * HP * MW);
    for (int idx = t; idx < HP * 8; idx += 256) {
        int h = idx >> 3, kq = idx & 7;
        *reinterpret_cast<uint4*>(&sBw[h * 40 + kq * 4]) = xp[idx];
    }
    __syncthreads();
    int lane = t & 31, wid = t >> 5;                     // wid = mt
    int c = lane & 3, r = lane >> 2;
    float acc[4][4];
#pragma unroll
    for (int nt = 0; nt < 4; ++nt) {
        acc[nt][0] = 0.f; acc[nt][1] = 0.f; acc[nt][2] = 0.f; acc[nt][3] = 0.f;
    }
#pragma unroll 3
    for (int kt = 0; kt < 33; ++kt) {
        uint4 fa = __ldg(&g_fhfh[(wid * 33 + kt) * 32 + lane]);
        int bw = (kt * 8 + c) * 40 + r;
#pragma unroll
        for (int nt = 0; nt < 4; ++nt) {
            unsigned b0 = sBw[bw + nt * 8];
            unsigned b1 = sBw[bw + 4 * 40 + nt * 8];
            mma_f16(acc[nt], fa.x, fa.y, fa.z, fa.w, b0, b1);
        }
    }
    int row0 = wid * 16 + r, row1 = row0 + 8;
#pragma unroll
    for (int nt = 0; nt < 4; ++nt) {
        int kxa = nt * 8 + 2 * c;
        *reinterpret_cast<float2*>(&g_x2r[((size_t)bc * 128 + row0) * 32 + kxa]) =
            make_float2(acc[nt][0], acc[nt][1]);
        *reinterpret_cast<float2*>(&g_x2r[((size_t)bc * 128 + row1) * 32 + kxa]) =
            make_float2(acc[nt][2], acc[nt][3]);
    }
}

// ---------------- K3: per-mode channel mixing (x2 -> y2) -------------------
// block = (jj, b-pair, o-half): 512 blocks; each thread does 4 o's x 2 batches
__global__ __launch_bounds__(256) void k3_mix(const float* __restrict__ spw1,
                                              const float* __restrict__ spw2, int l) {
    __shared__ float2 sX[2 * 64 * 32];                   // [b2][i][kx] 32 KB
    int blk = blockIdx.x;
    int jj = blk >> 3, bp = (blk >> 1) & 3, oh = blk & 1;
    int b0 = bp * 2;
    int t = threadIdx.x, kx = t & 31, sub = t >> 5;
    for (int idx = t; idx < 4096; idx += 256) {
        int bi = idx >> 11, rest = idx & 2047;
        int i = rest >> 5, kxl = rest & 31;
        const float* pp = g_x2r + ((size_t)((b0 + bi) * CW + i) * 128 + 2 * jj) * 32;
        sX[idx] = make_float2(pp[kxl], pp[32 + kxl]);
    }
    __syncthreads();
    const float2* wp; int jx;
    if (jj < 32) { wp = (const float2*)spw1; jx = jj; }
    else         { wp = (const float2*)spw2; jx = jj - 32; }
    size_t wbase = (size_t)l * 4194304 + (size_t)jx * 32 + kx;
    int obase = oh * 32 + sub * 4;
    float2 a0[4], a1[4];
#pragma unroll
    for (int q = 0; q < 4; ++q) { a0[q] = make_float2(0.f, 0.f); a1[q] = make_float2(0.f, 0.f); }
#pragma unroll 4
    for (int i = 0; i < 64; ++i) {
        float2 x0 = sX[i * 32 + kx];
        float2 x1 = sX[2048 + i * 32 + kx];
        size_t row = wbase + (size_t)(i * 64 + obase) * 1024;
#pragma unroll
        for (int q = 0; q < 4; ++q) {
            float2 c = __ldg(&wp[row + (size_t)q * 1024]);
            a0[q].x = fmaf(x0.x, c.x, a0[q].x); a0[q].x = fmaf(-x0.y, c.y, a0[q].x);
            a0[q].y = fmaf(x0.x, c.y, a0[q].y); a0[q].y = fmaf( x0.y, c.x, a0[q].y);
            a1[q].x = fmaf(x1.x, c.x, a1[q].x); a1[q].x = fmaf(-x1.y, c.y, a1[q].x);
            a1[q].y = fmaf(x1.x, c.y, a1[q].y); a1[q].y = fmaf( x1.y, c.x, a1[q].y);
        }
    }
#pragma unroll
    for (int q = 0; q < 4; ++q) {
        int o = obase + q;
        g_y2[(((size_t)b0       * CW + o) * MH + jj) * MW + kx] = a0[q];
        g_y2[(((size_t)(b0 + 1) * CW + o) * MH + jj) * MW + kx] = a1[q];
    }
}

// ---------------- K4: inverse H-DFT via fp16 mma ---------------------------
// per (b,o): C[528 h'][32 kx] = A[528][128] x B[128][32]; A const (g_ghfh)
__global__ __launch_bounds__(256) void k4_invh() {
    __shared__ unsigned sBw[64 * 40];
    int bo = blockIdx.x, b = bo >> 6, o = bo & 63;
    int t = threadIdx.x;
    const float2* yp = g_y2 + (size_t)bo * MH * MW;
    for (int idx = t; idx < MH * MW; idx += 256) {
        int j = idx >> 5, kx = idx & 31;
        float2 v = yp[idx];
        sBw[j * 40 + kx] = packh(v.x, v.y);
    }
    __syncthreads();
    int lane = t & 31, wid = t >> 5;
    int c = lane & 3, r = lane >> 2;
    for (int mt = wid; mt < 33; mt += 8) {
        float acc[4][4];
#pragma unroll
        for (int nt = 0; nt < 4; ++nt) {
            acc[nt][0] = 0.f; acc[nt][1] = 0.f; acc[nt][2] = 0.f; acc[nt][3] = 0.f;
        }
#pragma unroll
        for (int kt = 0; kt < 8; ++kt) {
            uint4 fa = __ldg(&g_ghfh[(mt * 8 + kt) * 32 + lane]);
            int bw = (kt * 8 + c) * 40 + r;
#pragma unroll
            for (int nt = 0; nt < 4; ++nt) {
                unsigned b0 = sBw[bw + nt * 8];
                unsigned b1 = sBw[bw + 4 * 40 + nt * 8];
                mma_f16(acc[nt], fa.x, fa.y, fa.z, fa.w, b0, b1);
            }
        }
        int h0a = mt * 16 + r, h0b = h0a + 8;
        int ha = h0a >> 1, pa = h0a & 1;
        int hb2 = h0b >> 1, pb = h0b & 1;
        size_t basea = ((size_t)(b * HP + ha) * 64 + o) * 64 + pa;
        size_t baseb = ((size_t)(b * HP + hb2) * 64 + o) * 64 + pb;
#pragma unroll
        for (int nt = 0; nt < 4; ++nt) {
            int kka = 2 * (nt * 8 + 2 * c);
            g_y1h[basea + kka]     = __float2half_rn(acc[nt][0]);
            g_y1h[basea + kka + 2] = __float2half_rn(acc[nt][1]);
            g_y1h[baseb + kka]     = __float2half_rn(acc[nt][2]);
            g_y1h[baseb + kka + 2] = __float2half_rn(acc[nt][3]);
        }
    }
}

// ---------------- K5: fp16 mma GEMM + fused W-DFT of the output ------------
// sT tile aliases sBw (all sBw reads complete before epilogue writes sT)
__global__ __launch_bounds__(256, 2)
void k5_combine(int cur, const float* __restrict__ cw,
                const float* __restrict__ cb, int l,
                float* __restrict__ out) {
    extern __shared__ unsigned s_raw_u[];
    unsigned* sAw = s_raw_u;                      // [o][kpair] stride 68 words
    unsigned* sBw = s_raw_u + 64 * 68;            // [kpair][w] stride 264 (+16 slack)
    unsigned* sT  = sBw;                          // ALIAS: out tile [o][w-pair]
    int bh = blockIdx.x;
    int b = bh / HP, h = bh - b * HP;
    bool last = (l == NL - 1);
    if (last && h >= H0) return;
    int t = threadIdx.x;
    // stage B (conv half k<64): channel pairs (2kp, 2kp+1), fp16 source
    {
        const __half* hb = g_hh[cur] + ((size_t)b * CW * HP + h) * WP;
        const size_t rstride = (size_t)HP * WP;
        for (int idx = t; idx < 32 * 66; idx += 256) {
            int kp = idx / 66, cq = idx - kp * 66;
            const unsigned* r0 = reinterpret_cast<const unsigned*>(hb + (size_t)(2 * kp) * rstride);
            const unsigned* r1 = reinterpret_cast<const unsigned*>(hb + (size_t)(2 * kp + 1) * rstride);
            uint2 u0 = *reinterpret_cast<const uint2*>(&r0[cq * 2]);
            uint2 u1 = *reinterpret_cast<const uint2*>(&r1[cq * 2]);
            int wb = kp * 264 + cq * 4;
            sBw[wb]     = __byte_perm(u0.x, u1.x, 0x5410);
            sBw[wb + 1] = __byte_perm(u0.x, u1.x, 0x7632);
            sBw[wb + 2] = __byte_perm(u0.y, u1.y, 0x5410);
            sBw[wb + 3] = __byte_perm(u0.y, u1.y, 0x7632);
        }
        if (t < 16) sBw[32 * 264 + t] = 0u;
    }
    // stage A: conv weights (fp32 src) + spectral coeffs (fp16 src, direct copy)
    {
        const float* cwl = cw + (size_t)l * 4096;
        for (int idx = t; idx < 2048; idx += 256) {
            int o = idx >> 5, ip = idx & 31;
            sAw[o * 68 + ip] = packh(cwl[o * 64 + 2 * ip], cwl[o * 64 + 2 * ip + 1]);
        }
        const unsigned* yb = reinterpret_cast<const unsigned*>(
            g_y1h + (size_t)(b * HP + h) * 4096);
        for (int idx = t; idx < 2048; idx += 256) {
            int o = idx >> 5, kp = idx & 31;
            sAw[o * 68 + 32 + kp] = yb[o * 32 + kp];
        }
    }
    __syncthreads();
    int lane = t & 31, wid = t >> 5;
    int mi = wid & 3, nh = wid >> 2;
    int m0 = mi * 16;
    int c = lane & 3, r = lane >> 2;
    int ntBeg = nh * 17;
    float acc[17][4];
#pragma unroll
    for (int j = 0; j < 17; ++j) {
        acc[j][0] = 0.f; acc[j][1] = 0.f; acc[j][2] = 0.f; acc[j][3] = 0.f;
    }
    int aw0 = (m0 + r) * 68 + c;
    int aw1 = aw0 + 8 * 68;
    // conv half (kt 0..3): B from smem
#pragma unroll
    for (int kt = 0; kt < 4; ++kt) {
        unsigned a0 = sAw[aw0 + kt * 8];
        unsigned a1 = sAw[aw1 + kt * 8];
        unsigned a2 = sAw[aw0 + kt * 8 + 4];
        unsigned a3 = sAw[aw1 + kt * 8 + 4];
        int bw = (kt * 8 + c) * 264 + r + ntBeg * 8;
#pragma unroll
        for (int j = 0; j < 17; ++j) {
            unsigned b0 = sBw[bw + j * 8];
            unsigned b1 = sBw[bw + 4 * 264 + j * 8];
            mma_f16(acc[j], a0, a1, a2, a3, b0, b1);
        }
    }
    // spectral half (kt 4..7): B frags pre-swizzled in g_awfh
#pragma unroll
    for (int kt = 4; kt < 8; ++kt) {
        unsigned a0 = sAw[aw0 + kt * 8];
        unsigned a1 = sAw[aw1 + kt * 8];
        unsigned a2 = sAw[aw0 + kt * 8 + 4];
        unsigned a3 = sAw[aw1 + kt * 8 + 4];
        const uint2* bp = &g_awfh[((kt - 4) * 34 + ntBeg) * 32 + lane];
#pragma unroll
        for (int j = 0; j < 17; ++j) {
            uint2 bb = __ldg(&bp[j * 32]);
            mma_f16(acc[j], a0, a1, a2, a3, bb.x, bb.y);
        }
    }
    // all sBw reads done; sT may now overwrite it
    __syncthreads();
    int o0 = m0 + r, o1 = o0 + 8;
    float bias0 = __ldg(&cb[l * 64 + o0]);
    float bias1 = __ldg(&cb[l * 64 + o1]);
    __half* hn = g_hh[cur ^ 1];
#pragma unroll
    for (int j = 0; j < 17; ++j) {
        if (nh && j == 16) continue;
        int n0 = (ntBeg + j) * 8;
        int wcol = n0 + 2 * c;
        float2 p0 = make_float2(acc[j][0] + bias0, acc[j][1] + bias0);
        float2 p1 = make_float2(acc[j][2] + bias1, acc[j][3] + bias1);
        if (!last) {
            p0.x = gelu_f(p0.x); p0.y = gelu_f(p0.y);
            p1.x = gelu_f(p1.x); p1.y = gelu_f(p1.y);
            unsigned u0 = packh(p0.x, p0.y);
            unsigned u1 = packh(p1.x, p1.y);
            *reinterpret_cast<unsigned*>(
                &hn[(((size_t)b * CW + o0) * HP + h) * WP + wcol]) = u0;
            *reinterpret_cast<unsigned*>(
                &hn[(((size_t)b * CW + o1) * HP + h) * WP + wcol]) = u1;
            int wword = 4 * (ntBeg + j) + c;
            sT[o0 * 132 + wword] = u0;
            sT[o1 * 132 + wword] = u1;
        } else if (n0 < W0) {
            *reinterpret_cast<float2*>(
                &out[(((size_t)b * CW + o0) * H0 + h) * W0 + wcol]) = p0;
            *reinterpret_cast<float2*>(
                &out[(((size_t)b * CW + o1) * H0 + h) * W0 + wcol]) = p1;
        }
    }
    if (!last) {
        if (t < 8) sT[64 * 132 + t] = 0u;
        __syncthreads();
        // fused W-DFT of the freshly computed field row-block (next layer's x1)
        float fac[4][4];
#pragma unroll
        for (int j = 0; j < 4; ++j) {
            fac[j][0] = 0.f; fac[j][1] = 0.f; fac[j][2] = 0.f; fac[j][3] = 0.f;
        }
        int fa0 = (m0 + r) * 132 + c;
        int fa1 = fa0 + 8 * 132;
#pragma unroll 4
        for (int kt = 0; kt < 17; ++kt) {
            unsigned a0 = sT[fa0 + kt * 8];
            unsigned a1 = sT[fa1 + kt * 8];
            unsigned a2 = sT[fa0 + kt * 8 + 4];
            unsigned a3 = sT[fa1 + kt * 8 + 4];
            const uint2* bp = &g_fwfh[(kt * 8 + nh * 4) * 32 + lane];
#pragma unroll
            for (int j = 0; j < 4; ++j) {
                uint2 bb = __ldg(&bp[j * 32]);
                mma_f16(fac[j], a0, a1, a2, a3, bb.x, bb.y);
            }
        }
        size_t rowc = (size_t)b * CW + m0 + r;
#pragma unroll
        for (int j = 0; j < 4; ++j) {
            int kx = (nh * 4 + j) * 4 + c;
            g_x1h[(rowc * HP + h) * MW + kx]       = packh(fac[j][0], fac[j][1]);
            g_x1h[((rowc + 8) * HP + h) * MW + kx] = packh(fac[j][2], fac[j][3]);
        }
    }
}

// ---------------- launch ---------------------------------------------------
extern "C" void kernel_launch(void* const* d_in, const int* in_sizes, int n_in,
                              void* d_out, int out_size) {
    const float* x   = (const float*)d_in[0];
    const float* lw1 = (const float*)d_in[1];
    const float* lb1 = (const float*)d_in[2];
    const float* lw2 = (const float*)d_in[3];
    const float* lb2 = (const float*)d_in[4];
    const float* cw  = (const float*)d_in[5];
    const float* cb  = (const float*)d_in[6];
    const float* sp1 = (const float*)d_in[7];
    const float* sp2 = (const float*)d_in[8];
    float* out = (float*)d_out;

    const int SMEM_K2 = 264 * 40 * 4;                      // 42240
    const int SMEM_K5 = (64 * 68 + 32 * 264 + 16) * 4;     // 51264 (sT aliases sBw)

    cudaFuncSetAttribute(k2_hdft,    cudaFuncAttributeMaxDynamicSharedMemorySize, SMEM_K2);
    cudaFuncSetAttribute(k5_combine, cudaFuncAttributeMaxDynamicSharedMemorySize, SMEM_K5);

    k_init<<<66, 256>>>();
    k_zero_pad<<<BATCH * CW, 256>>>();
    k_lift<<<BATCH * 256, 256>>>(x, lw1, lb1, lw2, lb2);

    for (int l = 0; l < NL; ++l) {
        int cur = l & 1;
        k2_hdft<<<BATCH * CW, 256, SMEM_K2>>>();
        k3_mix<<<MH * 8, 256>>>(sp1, sp2, l);
        k4_invh<<<BATCH * CW, 256>>>();
        k5_combine<<<BATCH * HP, 256, SMEM_K5>>>(cur, cw, cb, l, out);
    }
}

// round 15
// speedup vs baseline: 1.2011x; 1.0646x over previous
#include <cuda_runtime.h>
#include <cuda_fp16.h>
#include <math.h>

#define BATCH 8
#define CW    64
#define H0    256
#define W0    256
#define HP    264
#define WP    264
#define MW    32      // kept kx modes
#define MH    64      // kept ky modes (32 top + 32 bottom)
#define NL    4
#define HW    (HP*WP)            // 69696
#define NPIX  (BATCH*CW*HW)      // 35684352

// ---------------- scratch (device globals; no allocation allowed) ----------
__device__ __align__(128) __half   g_hh[2][NPIX];           // 2 x 71.4 MB
__device__ __align__(128) unsigned g_x1h[BATCH*CW*HP*MW];   // 17.3 MB packed (re,im)
__device__ __align__(128) float    g_x2r[BATCH*CW*128*32];  // 8.4 MB (split re/im rows)
__device__ __align__(128) float2   g_y2[BATCH*CW*MH*MW];    // 8.4 MB
__device__ __align__(128) __half   g_y1h[BATCH*HP*64*64];   // 17.3 MB [b][h][o][kk]
// fp16 fragment tables (k16)
__device__ __align__(128) uint2 g_fwfh[17*8*32];            // W-DFT B frags
__device__ __align__(128) uint2 g_awfh[4*34*32];            // c2r invW B frags
__device__ __align__(128) uint4 g_fhfh[8*33*32];            // H-DFT A frags
__device__ __align__(128) uint4 g_ghfh[33*8*32];            // invH A frags

__device__ __forceinline__ float gelu_f(float v) {
    return 0.5f * v * (1.0f + erff(v * 0.70710678118654752f));
}

__device__ __forceinline__ unsigned packh(float a, float b) {
    __half2 h = __halves2half2(__float2half_rn(a), __float2half_rn(b));
    return *reinterpret_cast<unsigned*>(&h);
}

// mma.m16n8k16 fp16 in, fp32 accum
__device__ __forceinline__ void mma_f16(float* d, unsigned a0, unsigned a1,
                                        unsigned a2, unsigned a3,
                                        unsigned b0, unsigned b1) {
    asm("mma.sync.aligned.m16n8k16.row.col.f32.f16.f16.f32 "
        "{%0,%1,%2,%3}, {%4,%5,%6,%7}, {%8,%9}, {%0,%1,%2,%3};"
        : "+f"(d[0]), "+f"(d[1]), "+f"(d[2]), "+f"(d[3])
        : "r"(a0), "r"(a1), "r"(a2), "r"(a3), "r"(b0), "r"(b1));
}

#define TWO_PI_D 6.283185307179586476925286766559
#define W_STEP   ((float)(TWO_PI_D / (double)WP))
#define H_STEP   ((float)(TWO_PI_D / (double)HP))

__device__ __forceinline__ float fwB_val(int n, int w) {
    if (w >= WP) return 0.f;
    int kx = n >> 1, p = n & 1;
    int m = (w * kx) % WP;
    float s, c; __sincosf((float)m * W_STEP, &s, &c);
    return p ? -s : c;
}
__device__ __forceinline__ float awB_val(int kk, int w) {
    if (w >= WP) return 0.f;
    int k = kk >> 1;
    float sc = ((k == 0) ? 1.0f : 2.0f) * (float)(1.0 / ((double)HP * (double)WP));
    int m = (k * w) % WP;
    float s, c; __sincosf((float)m * W_STEP, &s, &c);
    return (kk & 1) ? (-sc * s) : (sc * c);
}
__device__ __forceinline__ float fh_val(int jp, int kp) {
    int j = jp >> 1, pj = jp & 1, h = kp >> 1, ph = kp & 1;
    int ky = (j < 32) ? j : j + (HP - MH);
    int m = (h * ky) % HP;
    float s, c; __sincosf((float)m * H_STEP, &s, &c);
    return pj ? (ph ? c : -s) : (ph ? s : c);
}
__device__ __forceinline__ float gh_val(int hpp, int jp) {
    int h = hpp >> 1, ph = hpp & 1, j = jp >> 1, pj = jp & 1;
    int ky = (j < 32) ? j : j + (HP - MH);
    int m = (h * ky) % HP;
    float s, c; __sincosf((float)m * H_STEP, &s, &c);
    return ph ? (pj ? c : s) : (pj ? -s : c);
}

// ---------------- fragment-table init (fp32 trig, 1 item/thread) ----------
__global__ void k_init() {
    int i = blockIdx.x * 256 + threadIdx.x;               // 0..25599
    if (i < 4352) {             // g_fwfh [kt][nt][lane]
        int kt = i >> 8, rem = i & 255;
        int nt = rem >> 5, lane = rem & 31;
        int r = lane >> 2, c = lane & 3;
        int n = nt * 8 + r;
        int w0 = kt * 16 + 2 * c;
        g_fwfh[i] = make_uint2(packh(fwB_val(n, w0),     fwB_val(n, w0 + 1)),
                               packh(fwB_val(n, w0 + 8), fwB_val(n, w0 + 9)));
    } else if (i < 8704) {      // g_awfh [kt][ntg][lane]
        int j = i - 4352;
        int kt = j / (34 * 32), rem = j - kt * (34 * 32);
        int ntg = rem >> 5, lane = rem & 31;
        int r = lane >> 2, c = lane & 3;
        int w = ntg * 8 + r;
        int kk0 = kt * 16 + 2 * c;
        g_awfh[j] = make_uint2(packh(awB_val(kk0, w),     awB_val(kk0 + 1, w)),
                               packh(awB_val(kk0 + 8, w), awB_val(kk0 + 9, w)));
    } else if (i < 17152) {     // g_fhfh [mt][kt][lane]
        int j = i - 8704;
        int mt = j / (33 * 32), rem = j - mt * (33 * 32);
        int kt = rem >> 5, lane = rem & 31;
        int r = lane >> 2, c = lane & 3;
        int row0 = mt * 16 + r, k0 = kt * 16 + 2 * c;
        g_fhfh[j] = make_uint4(
            packh(fh_val(row0, k0),         fh_val(row0, k0 + 1)),
            packh(fh_val(row0 + 8, k0),     fh_val(row0 + 8, k0 + 1)),
            packh(fh_val(row0, k0 + 8),     fh_val(row0, k0 + 9)),
            packh(fh_val(row0 + 8, k0 + 8), fh_val(row0 + 8, k0 + 9)));
    } else {                    // g_ghfh [mt][kt][lane]
        int j = i - 17152;
        int mt = j >> 8, rem = j & 255;
        int kt = rem >> 5, lane = rem & 31;
        int r = lane >> 2, c = lane & 3;
        int row0 = mt * 16 + r, k0 = kt * 16 + 2 * c;
        g_ghfh[j] = make_uint4(
            packh(gh_val(row0, k0),         gh_val(row0, k0 + 1)),
            packh(gh_val(row0 + 8, k0),     gh_val(row0 + 8, k0 + 1)),
            packh(gh_val(row0, k0 + 8),     gh_val(row0, k0 + 9)),
            packh(gh_val(row0 + 8, k0 + 8), gh_val(row0 + 8, k0 + 9)));
    }
}

// Zero pad region of g_hh[0] + x1 pad rows (h >= H0) for layer 0
__global__ void k_zero_pad() {
    __half* p = g_hh[0] + (size_t)blockIdx.x * HW;
    int t = threadIdx.x;
    __half z = __float2half_rn(0.f);
    for (int i = t; i < 8 * WP; i += 256)
        p[(H0 + i / WP) * WP + (i % WP)] = z;
    for (int i = t; i < 8 * H0; i += 256)
        p[(i >> 3) * WP + W0 + (i & 7)] = z;
    unsigned* xr = g_x1h + ((size_t)blockIdx.x * HP + H0) * MW;
    for (int i = t; i < 8 * MW; i += 256) xr[i] = 0u;
}

// ---------------- lift (+fused W-DFT for layer 0) --------------------------
__global__ __launch_bounds__(256) void k_lift(
        const float* __restrict__ x,
        const float* __restrict__ w1, const float* __restrict__ b1,
        const float* __restrict__ w2, const float* __restrict__ b2) {
    __shared__ float sw1[160], sb1[32], sw2[2048], sb2[64];
    __shared__ unsigned sT[64 * 132 + 8];                // fp16 tile [o][w-pair]
    int t = threadIdx.x;
    if (t < 160) sw1[t] = w1[t];
    if (t < 32)  sb1[t] = b1[t];
    for (int i = t; i < 2048; i += 256) sw2[i] = w2[i];
    if (t < 64)  sb2[t] = b2[t];
    __syncthreads();
    int b = blockIdx.x >> 8, h = blockIdx.x & 255, w = t;
    float in5[5];
#pragma unroll
    for (int c = 0; c < 3; ++c)
        in5[c] = x[(((size_t)b * 3 + c) * H0 + h) * W0 + w];
    in5[3] = (float)h * (1.0f / 255.0f);
    in5[4] = (float)w * (1.0f / 255.0f);
    float mid[32];
#pragma unroll
    for (int o = 0; o < 32; ++o) {
        float s = sb1[o];
#pragma unroll
        for (int i = 0; i < 5; ++i) s = fmaf(sw1[o * 5 + i], in5[i], s);
        mid[o] = gelu_f(s);
    }
    __half* hb = g_hh[0];
    __half* sTh = reinterpret_cast<__half*>(sT);
#pragma unroll 4
    for (int o = 0; o < 64; ++o) {
        float s = sb2[o];
#pragma unroll
        for (int i = 0; i < 32; ++i) s = fmaf(sw2[o * 32 + i], mid[i], s);
        __half hv = __float2half_rn(s);
        hb[(((size_t)b * CW + o) * HP + h) * WP + w] = hv;
        sTh[o * 264 + w] = hv;
    }
    __half z = __float2half_rn(0.f);
    for (int i = t; i < 64 * 8; i += 256)
        sTh[(i >> 3) * 264 + 256 + (i & 7)] = z;         // pad w 256..263
    if (t < 8) sT[64 * 132 + t] = 0u;
    __syncthreads();
    // fused W-DFT (identical math to standalone k1)
    int lane = t & 31, wid = t >> 5;
    int mi = wid & 3, nh = wid >> 2;
    int m0 = mi * 16;
    int c = lane & 3, r = lane >> 2;
    float acc[4][4];
#pragma unroll
    for (int j = 0; j < 4; ++j) {
        acc[j][0] = 0.f; acc[j][1] = 0.f; acc[j][2] = 0.f; acc[j][3] = 0.f;
    }
    int aw0 = (m0 + r) * 132 + c;
    int aw1 = aw0 + 8 * 132;
#pragma unroll 4
    for (int kt = 0; kt < 17; ++kt) {
        unsigned a0 = sT[aw0 + kt * 8];
        unsigned a1 = sT[aw1 + kt * 8];
        unsigned a2 = sT[aw0 + kt * 8 + 4];
        unsigned a3 = sT[aw1 + kt * 8 + 4];
        const uint2* bp = &g_fwfh[(kt * 8 + nh * 4) * 32 + lane];
#pragma unroll
        for (int j = 0; j < 4; ++j) {
            uint2 bb = __ldg(&bp[j * 32]);
            mma_f16(acc[j], a0, a1, a2, a3, bb.x, bb.y);
        }
    }
    size_t rowc = (size_t)b * CW + m0 + r;
#pragma unroll
    for (int j = 0; j < 4; ++j) {
        int kx = (nh * 4 + j) * 4 + c;
        g_x1h[(rowc * HP + h) * MW + kx]       = packh(acc[j][0], acc[j][1]);
        g_x1h[((rowc + 8) * HP + h) * MW + kx] = packh(acc[j][2], acc[j][3]);
    }
}

// ---------------- K2: H-DFT via fp16 mma -----------------------------------
// per (b,c): C[128 j'][32 kx] = A[128][528] x B[528][32]; A const (g_fhfh)
__global__ __launch_bounds__(256, 4) void k2_hdft() {
    extern __shared__ unsigned sBw[];                    // 264*40 words
    int bc = blockIdx.x;
    int t = threadIdx.x;
    const uint4* xp = reinterpret_cast<const uint4*>(g_x1h + (size_t)bc * HP * MW);
    for (int idx = t; idx < HP * 8; idx += 256) {
        int h = idx >> 3, kq = idx & 7;
        *reinterpret_cast<uint4*>(&sBw[h * 40 + kq * 4]) = xp[idx];
    }
    __syncthreads();
    int lane = t & 31, wid = t >> 5;                     // wid = mt
    int c = lane & 3, r = lane >> 2;
    float acc[4][4];
#pragma unroll
    for (int nt = 0; nt < 4; ++nt) {
        acc[nt][0] = 0.f; acc[nt][1] = 0.f; acc[nt][2] = 0.f; acc[nt][3] = 0.f;
    }
#pragma unroll 3
    for (int kt = 0; kt < 33; ++kt) {
        uint4 fa = __ldg(&g_fhfh[(wid * 33 + kt) * 32 + lane]);
        int bw = (kt * 8 + c) * 40 + r;
#pragma unroll
        for (int nt = 0; nt < 4; ++nt) {
            unsigned b0 = sBw[bw + nt * 8];
            unsigned b1 = sBw[bw + 4 * 40 + nt * 8];
            mma_f16(acc[nt], fa.x, fa.y, fa.z, fa.w, b0, b1);
        }
    }
    int row0 = wid * 16 + r, row1 = row0 + 8;
#pragma unroll
    for (int nt = 0; nt < 4; ++nt) {
        int kxa = nt * 8 + 2 * c;
        *reinterpret_cast<float2*>(&g_x2r[((size_t)bc * 128 + row0) * 32 + kxa]) =
            make_float2(acc[nt][0], acc[nt][1]);
        *reinterpret_cast<float2*>(&g_x2r[((size_t)bc * 128 + row1) * 32 + kxa]) =
            make_float2(acc[nt][2], acc[nt][3]);
    }
}

// ---------------- K3: per-mode channel mixing (x2 -> y2) -------------------
// block = (jj, b-pair, o-half): 512 blocks; each thread does 4 o's x 2 batches
__global__ __launch_bounds__(256) void k3_mix(const float* __restrict__ spw1,
                                              const float* __restrict__ spw2, int l) {
    __shared__ float2 sX[2 * 64 * 32];                   // [b2][i][kx] 32 KB
    int blk = blockIdx.x;
    int jj = blk >> 3, bp = (blk >> 1) & 3, oh = blk & 1;
    int b0 = bp * 2;
    int t = threadIdx.x, kx = t & 31, sub = t >> 5;
    for (int idx = t; idx < 4096; idx += 256) {
        int bi = idx >> 11, rest = idx & 2047;
        int i = rest >> 5, kxl = rest & 31;
        const float* pp = g_x2r + ((size_t)((b0 + bi) * CW + i) * 128 + 2 * jj) * 32;
        sX[idx] = make_float2(pp[kxl], pp[32 + kxl]);
    }
    __syncthreads();
    const float2* wp; int jx;
    if (jj < 32) { wp = (const float2*)spw1; jx = jj; }
    else         { wp = (const float2*)spw2; jx = jj - 32; }
    size_t wbase = (size_t)l * 4194304 + (size_t)jx * 32 + kx;
    int obase = oh * 32 + sub * 4;
    float2 a0[4], a1[4];
#pragma unroll
    for (int q = 0; q < 4; ++q) { a0[q] = make_float2(0.f, 0.f); a1[q] = make_float2(0.f, 0.f); }
#pragma unroll 4
    for (int i = 0; i < 64; ++i) {
        float2 x0 = sX[i * 32 + kx];
        float2 x1 = sX[2048 + i * 32 + kx];
        size_t row = wbase + (size_t)(i * 64 + obase) * 1024;
#pragma unroll
        for (int q = 0; q < 4; ++q) {
            float2 c = __ldg(&wp[row + (size_t)q * 1024]);
            a0[q].x = fmaf(x0.x, c.x, a0[q].x); a0[q].x = fmaf(-x0.y, c.y, a0[q].x);
            a0[q].y = fmaf(x0.x, c.y, a0[q].y); a0[q].y = fmaf( x0.y, c.x, a0[q].y);
            a1[q].x = fmaf(x1.x, c.x, a1[q].x); a1[q].x = fmaf(-x1.y, c.y, a1[q].x);
            a1[q].y = fmaf(x1.x, c.y, a1[q].y); a1[q].y = fmaf( x1.y, c.x, a1[q].y);
        }
    }
#pragma unroll
    for (int q = 0; q < 4; ++q) {
        int o = obase + q;
        g_y2[(((size_t)b0       * CW + o) * MH + jj) * MW + kx] = a0[q];
        g_y2[(((size_t)(b0 + 1) * CW + o) * MH + jj) * MW + kx] = a1[q];
    }
}

// ---------------- K4: inverse H-DFT via fp16 mma (mt split over 2 blocks) --
__global__ __launch_bounds__(256) void k4_invh() {
    __shared__ unsigned sBw[64 * 40];
    int blk = blockIdx.x;
    int bo = blk >> 1, half = blk & 1;
    int b = bo >> 6, o = bo & 63;
    int t = threadIdx.x;
    const float2* yp = g_y2 + (size_t)bo * MH * MW;
    for (int idx = t; idx < MH * MW; idx += 256) {
        int j = idx >> 5, kx = idx & 31;
        float2 v = yp[idx];
        sBw[j * 40 + kx] = packh(v.x, v.y);
    }
    __syncthreads();
    int lane = t & 31, wid = t >> 5;
    int c = lane & 3, r = lane >> 2;
    int mtEnd = half ? 33 : 16;
    for (int mt = wid + half * 16; mt < mtEnd; mt += 8) {
        float acc[4][4];
#pragma unroll
        for (int nt = 0; nt < 4; ++nt) {
            acc[nt][0] = 0.f; acc[nt][1] = 0.f; acc[nt][2] = 0.f; acc[nt][3] = 0.f;
        }
#pragma unroll
        for (int kt = 0; kt < 8; ++kt) {
            uint4 fa = __ldg(&g_ghfh[(mt * 8 + kt) * 32 + lane]);
            int bw = (kt * 8 + c) * 40 + r;
#pragma unroll
            for (int nt = 0; nt < 4; ++nt) {
                unsigned b0 = sBw[bw + nt * 8];
                unsigned b1 = sBw[bw + 4 * 40 + nt * 8];
                mma_f16(acc[nt], fa.x, fa.y, fa.z, fa.w, b0, b1);
            }
        }
        int h0a = mt * 16 + r, h0b = h0a + 8;
        int ha = h0a >> 1, pa = h0a & 1;
        int hb2 = h0b >> 1, pb = h0b & 1;
        size_t basea = ((size_t)(b * HP + ha) * 64 + o) * 64 + pa;
        size_t baseb = ((size_t)(b * HP + hb2) * 64 + o) * 64 + pb;
#pragma unroll
        for (int nt = 0; nt < 4; ++nt) {
            int kka = 2 * (nt * 8 + 2 * c);
            g_y1h[basea + kka]     = __float2half_rn(acc[nt][0]);
            g_y1h[basea + kka + 2] = __float2half_rn(acc[nt][1]);
            g_y1h[baseb + kka]     = __float2half_rn(acc[nt][2]);
            g_y1h[baseb + kka + 2] = __float2half_rn(acc[nt][3]);
        }
    }
}

// ---------------- K5: fp16 mma GEMM + fused W-DFT of the output ------------
// sT tile aliases sBw (all sBw reads complete before epilogue writes sT)
__global__ __launch_bounds__(256, 2)
void k5_combine(int cur, const float* __restrict__ cw,
                const float* __restrict__ cb, int l,
                float* __restrict__ out) {
    extern __shared__ unsigned s_raw_u[];
    unsigned* sAw = s_raw_u;                      // [o][kpair] stride 68 words
    unsigned* sBw = s_raw_u + 64 * 68;            // [kpair][w] stride 264 (+16 slack)
    unsigned* sT  = sBw;                          // ALIAS: out tile [o][w-pair]
    int bh = blockIdx.x;
    int b = bh / HP, h = bh - b * HP;
    bool last = (l == NL - 1);
    if (last && h >= H0) return;
    int t = threadIdx.x;
    // stage B (conv half k<64): channel pairs (2kp, 2kp+1), fp16 source
    {
        const __half* hb = g_hh[cur] + ((size_t)b * CW * HP + h) * WP;
        const size_t rstride = (size_t)HP * WP;
        for (int idx = t; idx < 32 * 66; idx += 256) {
            int kp = idx / 66, cq = idx - kp * 66;
            const unsigned* r0 = reinterpret_cast<const unsigned*>(hb + (size_t)(2 * kp) * rstride);
            const unsigned* r1 = reinterpret_cast<const unsigned*>(hb + (size_t)(2 * kp + 1) * rstride);
            uint2 u0 = *reinterpret_cast<const uint2*>(&r0[cq * 2]);
            uint2 u1 = *reinterpret_cast<const uint2*>(&r1[cq * 2]);
            int wb = kp * 264 + cq * 4;
            sBw[wb]     = __byte_perm(u0.x, u1.x, 0x5410);
            sBw[wb + 1] = __byte_perm(u0.x, u1.x, 0x7632);
            sBw[wb + 2] = __byte_perm(u0.y, u1.y, 0x5410);
            sBw[wb + 3] = __byte_perm(u0.y, u1.y, 0x7632);
        }
        if (t < 16) sBw[32 * 264 + t] = 0u;
    }
    // stage A: conv weights (fp32 src) + spectral coeffs (fp16 src, direct copy)
    {
        const float* cwl = cw + (size_t)l * 4096;
        for (int idx = t; idx < 2048; idx += 256) {
            int o = idx >> 5, ip = idx & 31;
            sAw[o * 68 + ip] = packh(cwl[o * 64 + 2 * ip], cwl[o * 64 + 2 * ip + 1]);
        }
        const unsigned* yb = reinterpret_cast<const unsigned*>(
            g_y1h + (size_t)(b * HP + h) * 4096);
        for (int idx = t; idx < 2048; idx += 256) {
            int o = idx >> 5, kp = idx & 31;
            sAw[o * 68 + 32 + kp] = yb[o * 32 + kp];
        }
    }
    __syncthreads();
    int lane = t & 31, wid = t >> 5;
    int mi = wid & 3, nh = wid >> 2;
    int m0 = mi * 16;
    int c = lane & 3, r = lane >> 2;
    int ntBeg = nh * 17;
    float acc[17][4];
#pragma unroll
    for (int j = 0; j < 17; ++j) {
        acc[j][0] = 0.f; acc[j][1] = 0.f; acc[j][2] = 0.f; acc[j][3] = 0.f;
    }
    int aw0 = (m0 + r) * 68 + c;
    int aw1 = aw0 + 8 * 68;
    // conv half (kt 0..3): B from smem
#pragma unroll
    for (int kt = 0; kt < 4; ++kt) {
        unsigned a0 = sAw[aw0 + kt * 8];
        unsigned a1 = sAw[aw1 + kt * 8];
        unsigned a2 = sAw[aw0 + kt * 8 + 4];
        unsigned a3 = sAw[aw1 + kt * 8 + 4];
        int bw = (kt * 8 + c) * 264 + r + ntBeg * 8;
#pragma unroll
        for (int j = 0; j < 17; ++j) {
            unsigned b0 = sBw[bw + j * 8];
            unsigned b1 = sBw[bw + 4 * 264 + j * 8];
            mma_f16(acc[j], a0, a1, a2, a3, b0, b1);
        }
    }
    // spectral half (kt 4..7): B frags pre-swizzled in g_awfh
#pragma unroll
    for (int kt = 4; kt < 8; ++kt) {
        unsigned a0 = sAw[aw0 + kt * 8];
        unsigned a1 = sAw[aw1 + kt * 8];
        unsigned a2 = sAw[aw0 + kt * 8 + 4];
        unsigned a3 = sAw[aw1 + kt * 8 + 4];
        const uint2* bp = &g_awfh[((kt - 4) * 34 + ntBeg) * 32 + lane];
#pragma unroll
        for (int j = 0; j < 17; ++j) {
            uint2 bb = __ldg(&bp[j * 32]);
            mma_f16(acc[j], a0, a1, a2, a3, bb.x, bb.y);
        }
    }
    // all sBw reads done; sT may now overwrite it
    __syncthreads();
    int o0 = m0 + r, o1 = o0 + 8;
    float bias0 = __ldg(&cb[l * 64 + o0]);
    float bias1 = __ldg(&cb[l * 64 + o1]);
    __half* hn = g_hh[cur ^ 1];
#pragma unroll
    for (int j = 0; j < 17; ++j) {
        if (nh && j == 16) continue;
        int n0 = (ntBeg + j) * 8;
        int wcol = n0 + 2 * c;
        float2 p0 = make_float2(acc[j][0] + bias0, acc[j][1] + bias0);
        float2 p1 = make_float2(acc[j][2] + bias1, acc[j][3] + bias1);
        if (!last) {
            p0.x = gelu_f(p0.x); p0.y = gelu_f(p0.y);
            p1.x = gelu_f(p1.x); p1.y = gelu_f(p1.y);
            unsigned u0 = packh(p0.x, p0.y);
            unsigned u1 = packh(p1.x, p1.y);
            *reinterpret_cast<unsigned*>(
                &hn[(((size_t)b * CW + o0) * HP + h) * WP + wcol]) = u0;
            *reinterpret_cast<unsigned*>(
                &hn[(((size_t)b * CW + o1) * HP + h) * WP + wcol]) = u1;
            int wword = 4 * (ntBeg + j) + c;
            sT[o0 * 132 + wword] = u0;
            sT[o1 * 132 + wword] = u1;
        } else if (n0 < W0) {
            *reinterpret_cast<float2*>(
                &out[(((size_t)b * CW + o0) * H0 + h) * W0 + wcol]) = p0;
            *reinterpret_cast<float2*>(
                &out[(((size_t)b * CW + o1) * H0 + h) * W0 + wcol]) = p1;
        }
    }
    if (!last) {
        if (t < 8) sT[64 * 132 + t] = 0u;
        __syncthreads();
        // fused W-DFT of the freshly computed field row-block (next layer's x1)
        float fac[4][4];
#pragma unroll
        for (int j = 0; j < 4; ++j) {
            fac[j][0] = 0.f; fac[j][1] = 0.f; fac[j][2] = 0.f; fac[j][3] = 0.f;
        }
        int fa0 = (m0 + r) * 132 + c;
        int fa1 = fa0 + 8 * 132;
#pragma unroll 4
        for (int kt = 0; kt < 17; ++kt) {
            unsigned a0 = sT[fa0 + kt * 8];
            unsigned a1 = sT[fa1 + kt * 8];
            unsigned a2 = sT[fa0 + kt * 8 + 4];
            unsigned a3 = sT[fa1 + kt * 8 + 4];
            const uint2* bp = &g_fwfh[(kt * 8 + nh * 4) * 32 + lane];
#pragma unroll
            for (int j = 0; j < 4; ++j) {
                uint2 bb = __ldg(&bp[j * 32]);
                mma_f16(fac[j], a0, a1, a2, a3, bb.x, bb.y);
            }
        }
        size_t rowc = (size_t)b * CW + m0 + r;
#pragma unroll
        for (int j = 0; j < 4; ++j) {
            int kx = (nh * 4 + j) * 4 + c;
            g_x1h[(rowc * HP + h) * MW + kx]       = packh(fac[j][0], fac[j][1]);
            g_x1h[((rowc + 8) * HP + h) * MW + kx] = packh(fac[j][2], fac[j][3]);
        }
    }
}

// ---------------- launch ---------------------------------------------------
extern "C" void kernel_launch(void* const* d_in, const int* in_sizes, int n_in,
                              void* d_out, int out_size) {
    const float* x   = (const float*)d_in[0];
    const float* lw1 = (const float*)d_in[1];
    const float* lb1 = (const float*)d_in[2];
    const float* lw2 = (const float*)d_in[3];
    const float* lb2 = (const float*)d_in[4];
    const float* cw  = (const float*)d_in[5];
    const float* cb  = (const float*)d_in[6];
    const float* sp1 = (const float*)d_in[7];
    const float* sp2 = (const float*)d_in[8];
    float* out = (float*)d_out;

    const int SMEM_K2 = 264 * 40 * 4;                      // 42240
    const int SMEM_K5 = (64 * 68 + 32 * 264 + 16) * 4;     // 51264 (sT aliases sBw)

    cudaFuncSetAttribute(k2_hdft,    cudaFuncAttributeMaxDynamicSharedMemorySize, SMEM_K2);
    cudaFuncSetAttribute(k5_combine, cudaFuncAttributeMaxDynamicSharedMemorySize, SMEM_K5);

    k_init<<<100, 256>>>();
    k_zero_pad<<<BATCH * CW, 256>>>();
    k_lift<<<BATCH * 256, 256>>>(x, lw1, lb1, lw2, lb2);

    for (int l = 0; l < NL; ++l) {
        int cur = l & 1;
        k2_hdft<<<BATCH * CW, 256, SMEM_K2>>>();
        k3_mix<<<MH * 8, 256>>>(sp1, sp2, l);
        k4_invh<<<BATCH * CW * 2, 256>>>();
        k5_combine<<<BATCH * HP, 256, SMEM_K5>>>(cur, cw, cb, l, out);
    }
}

// round 16
// speedup vs baseline: 1.2034x; 1.0019x over previous
#include <cuda_runtime.h>
#include <cuda_fp16.h>
#include <math.h>

#define BATCH 8
#define CW    64
#define H0    256
#define W0    256
#define HP    264
#define WP    264
#define MW    32      // kept kx modes
#define MH    64      // kept ky modes (32 top + 32 bottom)
#define NL    4
#define HW    (HP*WP)            // 69696
#define NPIX  (BATCH*CW*HW)      // 35684352

// ---------------- scratch (device globals; no allocation allowed) ----------
__device__ __align__(128) __half   g_hh[2][NPIX];           // 2 x 71.4 MB
__device__ __align__(128) unsigned g_x1h[BATCH*CW*HP*MW];   // 17.3 MB packed (re,im)
__device__ __align__(128) float    g_x2r[BATCH*CW*128*32];  // 8.4 MB (split re/im rows)
__device__ __align__(128) unsigned g_y2h[BATCH*CW*MH*MW];   // 4.2 MB packed (re,im)
__device__ __align__(128) __half   g_y1h[BATCH*HP*64*64];   // 17.3 MB [b][h][o][kk]
// fp16 fragment tables (k16)
__device__ __align__(128) uint2 g_fwfh[17*8*32];            // W-DFT B frags
__device__ __align__(128) uint2 g_awfh[4*34*32];            // c2r invW B frags
__device__ __align__(128) uint4 g_fhfh[8*33*32];            // H-DFT A frags
__device__ __align__(128) uint4 g_ghfh[33*8*32];            // invH A frags

__device__ __forceinline__ float gelu_f(float v) {
    return 0.5f * v * (1.0f + erff(v * 0.70710678118654752f));
}

__device__ __forceinline__ unsigned packh(float a, float b) {
    __half2 h = __halves2half2(__float2half_rn(a), __float2half_rn(b));
    return *reinterpret_cast<unsigned*>(&h);
}

// mma.m16n8k16 fp16 in, fp32 accum
__device__ __forceinline__ void mma_f16(float* d, unsigned a0, unsigned a1,
                                        unsigned a2, unsigned a3,
                                        unsigned b0, unsigned b1) {
    asm("mma.sync.aligned.m16n8k16.row.col.f32.f16.f16.f32 "
        "{%0,%1,%2,%3}, {%4,%5,%6,%7}, {%8,%9}, {%0,%1,%2,%3};"
        : "+f"(d[0]), "+f"(d[1]), "+f"(d[2]), "+f"(d[3])
        : "r"(a0), "r"(a1), "r"(a2), "r"(a3), "r"(b0), "r"(b1));
}

#define TWO_PI_D 6.283185307179586476925286766559
#define W_STEP   ((float)(TWO_PI_D / (double)WP))
#define H_STEP   ((float)(TWO_PI_D / (double)HP))

__device__ __forceinline__ float fwB_val(int n, int w) {
    if (w >= WP) return 0.f;
    int kx = n >> 1, p = n & 1;
    int m = (w * kx) % WP;
    float s, c; __sincosf((float)m * W_STEP, &s, &c);
    return p ? -s : c;
}
__device__ __forceinline__ float awB_val(int kk, int w) {
    if (w >= WP) return 0.f;
    int k = kk >> 1;
    float sc = ((k == 0) ? 1.0f : 2.0f) * (float)(1.0 / ((double)HP * (double)WP));
    int m = (k * w) % WP;
    float s, c; __sincosf((float)m * W_STEP, &s, &c);
    return (kk & 1) ? (-sc * s) : (sc * c);
}
__device__ __forceinline__ float fh_val(int jp, int kp) {
    int j = jp >> 1, pj = jp & 1, h = kp >> 1, ph = kp & 1;
    int ky = (j < 32) ? j : j + (HP - MH);
    int m = (h * ky) % HP;
    float s, c; __sincosf((float)m * H_STEP, &s, &c);
    return pj ? (ph ? c : -s) : (ph ? s : c);
}
__device__ __forceinline__ float gh_val(int hpp, int jp) {
    int h = hpp >> 1, ph = hpp & 1, j = jp >> 1, pj = jp & 1;
    int ky = (j < 32) ? j : j + (HP - MH);
    int m = (h * ky) % HP;
    float s, c; __sincosf((float)m * H_STEP, &s, &c);
    return ph ? (pj ? c : s) : (pj ? -s : c);
}

// ---------------- fragment-table init (fp32 trig, 1 item/thread) ----------
__global__ void k_init() {
    int i = blockIdx.x * 256 + threadIdx.x;               // 0..25599
    if (i < 4352) {             // g_fwfh [kt][nt][lane]
        int kt = i >> 8, rem = i & 255;
        int nt = rem >> 5, lane = rem & 31;
        int r = lane >> 2, c = lane & 3;
        int n = nt * 8 + r;
        int w0 = kt * 16 + 2 * c;
        g_fwfh[i] = make_uint2(packh(fwB_val(n, w0),     fwB_val(n, w0 + 1)),
                               packh(fwB_val(n, w0 + 8), fwB_val(n, w0 + 9)));
    } else if (i < 8704) {      // g_awfh [kt][ntg][lane]
        int j = i - 4352;
        int kt = j / (34 * 32), rem = j - kt * (34 * 32);
        int ntg = rem >> 5, lane = rem & 31;
        int r = lane >> 2, c = lane & 3;
        int w = ntg * 8 + r;
        int kk0 = kt * 16 + 2 * c;
        g_awfh[j] = make_uint2(packh(awB_val(kk0, w),     awB_val(kk0 + 1, w)),
                               packh(awB_val(kk0 + 8, w), awB_val(kk0 + 9, w)));
    } else if (i < 17152) {     // g_fhfh [mt][kt][lane]
        int j = i - 8704;
        int mt = j / (33 * 32), rem = j - mt * (33 * 32);
        int kt = rem >> 5, lane = rem & 31;
        int r = lane >> 2, c = lane & 3;
        int row0 = mt * 16 + r, k0 = kt * 16 + 2 * c;
        g_fhfh[j] = make_uint4(
            packh(fh_val(row0, k0),         fh_val(row0, k0 + 1)),
            packh(fh_val(row0 + 8, k0),     fh_val(row0 + 8, k0 + 1)),
            packh(fh_val(row0, k0 + 8),     fh_val(row0, k0 + 9)),
            packh(fh_val(row0 + 8, k0 + 8), fh_val(row0 + 8, k0 + 9)));
    } else {                    // g_ghfh [mt][kt][lane]
        int j = i - 17152;
        int mt = j >> 8, rem = j & 255;
        int kt = rem >> 5, lane = rem & 31;
        int r = lane >> 2, c = lane & 3;
        int row0 = mt * 16 + r, k0 = kt * 16 + 2 * c;
        g_ghfh[j] = make_uint4(
            packh(gh_val(row0, k0),         gh_val(row0, k0 + 1)),
            packh(gh_val(row0 + 8, k0),     gh_val(row0 + 8, k0 + 1)),
            packh(gh_val(row0, k0 + 8),     gh_val(row0, k0 + 9)),
            packh(gh_val(row0 + 8, k0 + 8), gh_val(row0 + 8, k0 + 9)));
    }
}

// Zero pad region of g_hh[0] + x1 pad rows (h >= H0) for layer 0
__global__ void k_zero_pad() {
    __half* p = g_hh[0] + (size_t)blockIdx.x * HW;
    int t = threadIdx.x;
    __half z = __float2half_rn(0.f);
    for (int i = t; i < 8 * WP; i += 256)
        p[(H0 + i / WP) * WP + (i % WP)] = z;
    for (int i = t; i < 8 * H0; i += 256)
        p[(i >> 3) * WP + W0 + (i & 7)] = z;
    unsigned* xr = g_x1h + ((size_t)blockIdx.x * HP + H0) * MW;
    for (int i = t; i < 8 * MW; i += 256) xr[i] = 0u;
}

// ---------------- lift (+fused W-DFT for layer 0) --------------------------
__global__ __launch_bounds__(256) void k_lift(
        const float* __restrict__ x,
        const float* __restrict__ w1, const float* __restrict__ b1,
        const float* __restrict__ w2, const float* __restrict__ b2) {
    __shared__ float sw1[160], sb1[32], sw2[2048], sb2[64];
    __shared__ unsigned sT[64 * 132 + 8];                // fp16 tile [o][w-pair]
    int t = threadIdx.x;
    if (t < 160) sw1[t] = w1[t];
    if (t < 32)  sb1[t] = b1[t];
    for (int i = t; i < 2048; i += 256) sw2[i] = w2[i];
    if (t < 64)  sb2[t] = b2[t];
    __syncthreads();
    int b = blockIdx.x >> 8, h = blockIdx.x & 255, w = t;
    float in5[5];
#pragma unroll
    for (int c = 0; c < 3; ++c)
        in5[c] = x[(((size_t)b * 3 + c) * H0 + h) * W0 + w];
    in5[3] = (float)h * (1.0f / 255.0f);
    in5[4] = (float)w * (1.0f / 255.0f);
    float mid[32];
#pragma unroll
    for (int o = 0; o < 32; ++o) {
        float s = sb1[o];
#pragma unroll
        for (int i = 0; i < 5; ++i) s = fmaf(sw1[o * 5 + i], in5[i], s);
        mid[o] = gelu_f(s);
    }
    __half* hb = g_hh[0];
    __half* sTh = reinterpret_cast<__half*>(sT);
#pragma unroll 4
    for (int o = 0; o < 64; ++o) {
        float s = sb2[o];
#pragma unroll
        for (int i = 0; i < 32; ++i) s = fmaf(sw2[o * 32 + i], mid[i], s);
        __half hv = __float2half_rn(s);
        hb[(((size_t)b * CW + o) * HP + h) * WP + w] = hv;
        sTh[o * 264 + w] = hv;
    }
    __half z = __float2half_rn(0.f);
    for (int i = t; i < 64 * 8; i += 256)
        sTh[(i >> 3) * 264 + 256 + (i & 7)] = z;         // pad w 256..263
    if (t < 8) sT[64 * 132 + t] = 0u;
    __syncthreads();
    // fused W-DFT (identical math to standalone k1)
    int lane = t & 31, wid = t >> 5;
    int mi = wid & 3, nh = wid >> 2;
    int m0 = mi * 16;
    int c = lane & 3, r = lane >> 2;
    float acc[4][4];
#pragma unroll
    for (int j = 0; j < 4; ++j) {
        acc[j][0] = 0.f; acc[j][1] = 0.f; acc[j][2] = 0.f; acc[j][3] = 0.f;
    }
    int aw0 = (m0 + r) * 132 + c;
    int aw1 = aw0 + 8 * 132;
#pragma unroll 4
    for (int kt = 0; kt < 17; ++kt) {
        unsigned a0 = sT[aw0 + kt * 8];
        unsigned a1 = sT[aw1 + kt * 8];
        unsigned a2 = sT[aw0 + kt * 8 + 4];
        unsigned a3 = sT[aw1 + kt * 8 + 4];
        const uint2* bp = &g_fwfh[(kt * 8 + nh * 4) * 32 + lane];
#pragma unroll
        for (int j = 0; j < 4; ++j) {
            uint2 bb = __ldg(&bp[j * 32]);
            mma_f16(acc[j], a0, a1, a2, a3, bb.x, bb.y);
        }
    }
    size_t rowc = (size_t)b * CW + m0 + r;
#pragma unroll
    for (int j = 0; j < 4; ++j) {
        int kx = (nh * 4 + j) * 4 + c;
        g_x1h[(rowc * HP + h) * MW + kx]       = packh(acc[j][0], acc[j][1]);
        g_x1h[((rowc + 8) * HP + h) * MW + kx] = packh(acc[j][2], acc[j][3]);
    }
}

// ---------------- K2: H-DFT via fp16 mma (A-frag prefetch depth 3) ---------
__global__ __launch_bounds__(256, 4) void k2_hdft() {
    extern __shared__ unsigned sBw[];                    // 264*40 words
    int bc = blockIdx.x;
    int t = threadIdx.x;
    const uint4* xp = reinterpret_cast<const uint4*>(g_x1h + (size_t)bc * HP * MW);
    for (int idx = t; idx < HP * 8; idx += 256) {
        int h = idx >> 3, kq = idx & 7;
        *reinterpret_cast<uint4*>(&sBw[h * 40 + kq * 4]) = xp[idx];
    }
    __syncthreads();
    int lane = t & 31, wid = t >> 5;                     // wid = mt
    int c = lane & 3, r = lane >> 2;
    float acc[4][4];
#pragma unroll
    for (int nt = 0; nt < 4; ++nt) {
        acc[nt][0] = 0.f; acc[nt][1] = 0.f; acc[nt][2] = 0.f; acc[nt][3] = 0.f;
    }
    const uint4* tab = &g_fhfh[wid * 33 * 32 + lane];
    uint4 f0 = __ldg(&tab[0]);
    uint4 f1 = __ldg(&tab[32]);
    uint4 f2 = __ldg(&tab[64]);
#pragma unroll 3
    for (int kt = 0; kt < 33; ++kt) {
        uint4 fa = f0; f0 = f1; f1 = f2;
        if (kt + 3 < 33) f2 = __ldg(&tab[(kt + 3) * 32]);
        int bw = (kt * 8 + c) * 40 + r;
#pragma unroll
        for (int nt = 0; nt < 4; ++nt) {
            unsigned b0 = sBw[bw + nt * 8];
            unsigned b1 = sBw[bw + 4 * 40 + nt * 8];
            mma_f16(acc[nt], fa.x, fa.y, fa.z, fa.w, b0, b1);
        }
    }
    int row0 = wid * 16 + r, row1 = row0 + 8;
#pragma unroll
    for (int nt = 0; nt < 4; ++nt) {
        int kxa = nt * 8 + 2 * c;
        *reinterpret_cast<float2*>(&g_x2r[((size_t)bc * 128 + row0) * 32 + kxa]) =
            make_float2(acc[nt][0], acc[nt][1]);
        *reinterpret_cast<float2*>(&g_x2r[((size_t)bc * 128 + row1) * 32 + kxa]) =
            make_float2(acc[nt][2], acc[nt][3]);
    }
}

// ---------------- K3: per-mode channel mixing (x2 -> y2h packed fp16) ------
// block = (jj, b-pair, o-half): 512 blocks; each thread does 4 o's x 2 batches
__global__ __launch_bounds__(256) void k3_mix(const float* __restrict__ spw1,
                                              const float* __restrict__ spw2, int l) {
    __shared__ float2 sX[2 * 64 * 32];                   // [b2][i][kx] 32 KB
    int blk = blockIdx.x;
    int jj = blk >> 3, bp = (blk >> 1) & 3, oh = blk & 1;
    int b0 = bp * 2;
    int t = threadIdx.x, kx = t & 31, sub = t >> 5;
    for (int idx = t; idx < 4096; idx += 256) {
        int bi = idx >> 11, rest = idx & 2047;
        int i = rest >> 5, kxl = rest & 31;
        const float* pp = g_x2r + ((size_t)((b0 + bi) * CW + i) * 128 + 2 * jj) * 32;
        sX[idx] = make_float2(pp[kxl], pp[32 + kxl]);
    }
    __syncthreads();
    const float2* wp; int jx;
    if (jj < 32) { wp = (const float2*)spw1; jx = jj; }
    else         { wp = (const float2*)spw2; jx = jj - 32; }
    size_t wbase = (size_t)l * 4194304 + (size_t)jx * 32 + kx;
    int obase = oh * 32 + sub * 4;
    float2 a0[4], a1[4];
#pragma unroll
    for (int q = 0; q < 4; ++q) { a0[q] = make_float2(0.f, 0.f); a1[q] = make_float2(0.f, 0.f); }
#pragma unroll 4
    for (int i = 0; i < 64; ++i) {
        float2 x0 = sX[i * 32 + kx];
        float2 x1 = sX[2048 + i * 32 + kx];
        size_t row = wbase + (size_t)(i * 64 + obase) * 1024;
#pragma unroll
        for (int q = 0; q < 4; ++q) {
            float2 c = __ldg(&wp[row + (size_t)q * 1024]);
            a0[q].x = fmaf(x0.x, c.x, a0[q].x); a0[q].x = fmaf(-x0.y, c.y, a0[q].x);
            a0[q].y = fmaf(x0.x, c.y, a0[q].y); a0[q].y = fmaf( x0.y, c.x, a0[q].y);
            a1[q].x = fmaf(x1.x, c.x, a1[q].x); a1[q].x = fmaf(-x1.y, c.y, a1[q].x);
            a1[q].y = fmaf(x1.x, c.y, a1[q].y); a1[q].y = fmaf( x1.y, c.x, a1[q].y);
        }
    }
#pragma unroll
    for (int q = 0; q < 4; ++q) {
        int o = obase + q;
        g_y2h[(((size_t)b0       * CW + o) * MH + jj) * MW + kx] = packh(a0[q].x, a0[q].y);
        g_y2h[(((size_t)(b0 + 1) * CW + o) * MH + jj) * MW + kx] = packh(a1[q].x, a1[q].y);
    }
}

// ---------------- K4: inverse H-DFT via fp16 mma (mt split over 2 blocks) --
__global__ __launch_bounds__(256) void k4_invh() {
    __shared__ unsigned sBw[64 * 40];
    int blk = blockIdx.x;
    int bo = blk >> 1, half = blk & 1;
    int b = bo >> 6, o = bo & 63;
    int t = threadIdx.x;
    const uint4* yp = reinterpret_cast<const uint4*>(g_y2h + (size_t)bo * MH * MW);
    for (int idx = t; idx < MH * 8; idx += 256) {
        int j = idx >> 3, kq = idx & 7;
        *reinterpret_cast<uint4*>(&sBw[j * 40 + kq * 4]) = yp[idx];
    }
    __syncthreads();
    int lane = t & 31, wid = t >> 5;
    int c = lane & 3, r = lane >> 2;
    int mtEnd = half ? 33 : 16;
    for (int mt = wid + half * 16; mt < mtEnd; mt += 8) {
        float acc[4][4];
#pragma unroll
        for (int nt = 0; nt < 4; ++nt) {
            acc[nt][0] = 0.f; acc[nt][1] = 0.f; acc[nt][2] = 0.f; acc[nt][3] = 0.f;
        }
#pragma unroll
        for (int kt = 0; kt < 8; ++kt) {
            uint4 fa = __ldg(&g_ghfh[(mt * 8 + kt) * 32 + lane]);
            int bw = (kt * 8 + c) * 40 + r;
#pragma unroll
            for (int nt = 0; nt < 4; ++nt) {
                unsigned b0 = sBw[bw + nt * 8];
                unsigned b1 = sBw[bw + 4 * 40 + nt * 8];
                mma_f16(acc[nt], fa.x, fa.y, fa.z, fa.w, b0, b1);
            }
        }
        int h0a = mt * 16 + r, h0b = h0a + 8;
        int ha = h0a >> 1, pa = h0a & 1;
        int hb2 = h0b >> 1, pb = h0b & 1;
        size_t basea = ((size_t)(b * HP + ha) * 64 + o) * 64 + pa;
        size_t baseb = ((size_t)(b * HP + hb2) * 64 + o) * 64 + pb;
#pragma unroll
        for (int nt = 0; nt < 4; ++nt) {
            int kka = 2 * (nt * 8 + 2 * c);
            g_y1h[basea + kka]     = __float2half_rn(acc[nt][0]);
            g_y1h[basea + kka + 2] = __float2half_rn(acc[nt][1]);
            g_y1h[baseb + kka]     = __float2half_rn(acc[nt][2]);
            g_y1h[baseb + kka + 2] = __float2half_rn(acc[nt][3]);
        }
    }
}

// ---------------- K5: fp16 mma GEMM + fused W-DFT of the output ------------
// sT tile aliases sBw (all sBw reads complete before epilogue writes sT)
__global__ __launch_bounds__(256, 2)
void k5_combine(int cur, const float* __restrict__ cw,
                const float* __restrict__ cb, int l,
                float* __restrict__ out) {
    extern __shared__ unsigned s_raw_u[];
    unsigned* sAw = s_raw_u;                      // [o][kpair] stride 68 words
    unsigned* sBw = s_raw_u + 64 * 68;            // [kpair][w] stride 264 (+16 slack)
    unsigned* sT  = sBw;                          // ALIAS: out tile [o][w-pair]
    int bh = blockIdx.x;
    int b = bh / HP, h = bh - b * HP;
    bool last = (l == NL - 1);
    if (last && h >= H0) return;
    int t = threadIdx.x;
    // stage B (conv half k<64): channel pairs (2kp, 2kp+1), fp16 source
    {
        const __half* hb = g_hh[cur] + ((size_t)b * CW * HP + h) * WP;
        const size_t rstride = (size_t)HP * WP;
        for (int idx = t; idx < 32 * 66; idx += 256) {
            int kp = idx / 66, cq = idx - kp * 66;
            const unsigned* r0 = reinterpret_cast<const unsigned*>(hb + (size_t)(2 * kp) * rstride);
            const unsigned* r1 = reinterpret_cast<const unsigned*>(hb + (size_t)(2 * kp + 1) * rstride);
            uint2 u0 = *reinterpret_cast<const uint2*>(&r0[cq * 2]);
            uint2 u1 = *reinterpret_cast<const uint2*>(&r1[cq * 2]);
            int wb = kp * 264 + cq * 4;
            sBw[wb]     = __byte_perm(u0.x, u1.x, 0x5410);
            sBw[wb + 1] = __byte_perm(u0.x, u1.x, 0x7632);
            sBw[wb + 2] = __byte_perm(u0.y, u1.y, 0x5410);
            sBw[wb + 3] = __byte_perm(u0.y, u1.y, 0x7632);
        }
        if (t < 16) sBw[32 * 264 + t] = 0u;
    }
    // stage A: conv weights (fp32 src) + spectral coeffs (fp16 src, direct copy)
    {
        const float* cwl = cw + (size_t)l * 4096;
        for (int idx = t; idx < 2048; idx += 256) {
            int o = idx >> 5, ip = idx & 31;
            sAw[o * 68 + ip] = packh(cwl[o * 64 + 2 * ip], cwl[o * 64 + 2 * ip + 1]);
        }
        const unsigned* yb = reinterpret_cast<const unsigned*>(
            g_y1h + (size_t)(b * HP + h) * 4096);
        for (int idx = t; idx < 2048; idx += 256) {
            int o = idx >> 5, kp = idx & 31;
            sAw[o * 68 + 32 + kp] = yb[o * 32 + kp];
        }
    }
    __syncthreads();
    int lane = t & 31, wid = t >> 5;
    int mi = wid & 3, nh = wid >> 2;
    int m0 = mi * 16;
    int c = lane & 3, r = lane >> 2;
    int ntBeg = nh * 17;
    float acc[17][4];
#pragma unroll
    for (int j = 0; j < 17; ++j) {
        acc[j][0] = 0.f; acc[j][1] = 0.f; acc[j][2] = 0.f; acc[j][3] = 0.f;
    }
    int aw0 = (m0 + r) * 68 + c;
    int aw1 = aw0 + 8 * 68;
    // conv half (kt 0..3): B from smem
#pragma unroll
    for (int kt = 0; kt < 4; ++kt) {
        unsigned a0 = sAw[aw0 + kt * 8];
        unsigned a1 = sAw[aw1 + kt * 8];
        unsigned a2 = sAw[aw0 + kt * 8 + 4];
        unsigned a3 = sAw[aw1 + kt * 8 + 4];
        int bw = (kt * 8 + c) * 264 + r + ntBeg * 8;
#pragma unroll
        for (int j = 0; j < 17; ++j) {
            unsigned b0 = sBw[bw + j * 8];
            unsigned b1 = sBw[bw + 4 * 264 + j * 8];
            mma_f16(acc[j], a0, a1, a2, a3, b0, b1);
        }
    }
    // spectral half (kt 4..7): B frags pre-swizzled in g_awfh
#pragma unroll
    for (int kt = 4; kt < 8; ++kt) {
        unsigned a0 = sAw[aw0 + kt * 8];
        unsigned a1 = sAw[aw1 + kt * 8];
        unsigned a2 = sAw[aw0 + kt * 8 + 4];
        unsigned a3 = sAw[aw1 + kt * 8 + 4];
        const uint2* bp = &g_awfh[((kt - 4) * 34 + ntBeg) * 32 + lane];
#pragma unroll
        for (int j = 0; j < 17; ++j) {
            uint2 bb = __ldg(&bp[j * 32]);
            mma_f16(acc[j], a0, a1, a2, a3, bb.x, bb.y);
        }
    }
    // all sBw reads done; sT may now overwrite it
    __syncthreads();
    int o0 = m0 + r, o1 = o0 + 8;
    float bias0 = __ldg(&cb[l * 64 + o0]);
    float bias1 = __ldg(&cb[l * 64 + o1]);
    __half* hn = g_hh[cur ^ 1];
#pragma unroll
    for (int j = 0; j < 17; ++j) {
        if (nh && j == 16) continue;
        int n0 = (ntBeg + j) * 8;
        int wcol = n0 + 2 * c;
        float2 p0 = make_float2(acc[j][0] + bias0, acc[j][1] + bias0);
        float2 p1 = make_float2(acc[j][2] + bias1, acc[j][3] + bias1);
        if (!last) {
            p0.x = gelu_f(p0.x); p0.y = gelu_f(p0.y);
            p1.x = gelu_f(p1.x); p1.y = gelu_f(p1.y);
            unsigned u0 = packh(p0.x, p0.y);
            unsigned u1 = packh(p1.x, p1.y);
            *reinterpret_cast<unsigned*>(
                &hn[(((size_t)b * CW + o0) * HP + h) * WP + wcol]) = u0;
            *reinterpret_cast<unsigned*>(
                &hn[(((size_t)b * CW + o1) * HP + h) * WP + wcol]) = u1;
            int wword = 4 * (ntBeg + j) + c;
            sT[o0 * 132 + wword] = u0;
            sT[o1 * 132 + wword] = u1;
        } else if (n0 < W0) {
            *reinterpret_cast<float2*>(
                &out[(((size_t)b * CW + o0) * H0 + h) * W0 + wcol]) = p0;
            *reinterpret_cast<float2*>(
                &out[(((size_t)b * CW + o1) * H0 + h) * W0 + wcol]) = p1;
        }
    }
    if (!last) {
        if (t < 8) sT[64 * 132 + t] = 0u;
        __syncthreads();
        // fused W-DFT of the freshly computed field row-block (next layer's x1)
        float fac[4][4];
#pragma unroll
        for (int j = 0; j < 4; ++j) {
            fac[j][0] = 0.f; fac[j][1] = 0.f; fac[j][2] = 0.f; fac[j][3] = 0.f;
        }
        int fa0 = (m0 + r) * 132 + c;
        int fa1 = fa0 + 8 * 132;
#pragma unroll 4
        for (int kt = 0; kt < 17; ++kt) {
            unsigned a0 = sT[fa0 + kt * 8];
            unsigned a1 = sT[fa1 + kt * 8];
            unsigned a2 = sT[fa0 + kt * 8 + 4];
            unsigned a3 = sT[fa1 + kt * 8 + 4];
            const uint2* bp = &g_fwfh[(kt * 8 + nh * 4) * 32 + lane];
#pragma unroll
            for (int j = 0; j < 4; ++j) {
                uint2 bb = __ldg(&bp[j * 32]);
                mma_f16(fac[j], a0, a1, a2, a3, bb.x, bb.y);
            }
        }
        size_t rowc = (size_t)b * CW + m0 + r;
#pragma unroll
        for (int j = 0; j < 4; ++j) {
            int kx = (nh * 4 + j) * 4 + c;
            g_x1h[(rowc * HP + h) * MW + kx]       = packh(fac[j][0], fac[j][1]);
            g_x1h[((rowc + 8) * HP + h) * MW + kx] = packh(fac[j][2], fac[j][3]);
        }
    }
}

// ---------------- launch ---------------------------------------------------
extern "C" void kernel_launch(void* const* d_in, const int* in_sizes, int n_in,
                              void* d_out, int out_size) {
    const float* x   = (const float*)d_in[0];
    const float* lw1 = (const float*)d_in[1];
    const float* lb1 = (const float*)d_in[2];
    const float* lw2 = (const float*)d_in[3];
    const float* lb2 = (const float*)d_in[4];
    const float* cw  = (const float*)d_in[5];
    const float* cb  = (const float*)d_in[6];
    const float* sp1 = (const float*)d_in[7];
    const float* sp2 = (const float*)d_in[8];
    float* out = (float*)d_out;

    const int SMEM_K2 = 264 * 40 * 4;                      // 42240
    const int SMEM_K5 = (64 * 68 + 32 * 264 + 16) * 4;     // 51264 (sT aliases sBw)

    cudaFuncSetAttribute(k2_hdft,    cudaFuncAttributeMaxDynamicSharedMemorySize, SMEM_K2);
    cudaFuncSetAttribute(k5_combine, cudaFuncAttributeMaxDynamicSharedMemorySize, SMEM_K5);

    k_init<<<100, 256>>>();
    k_zero_pad<<<BATCH * CW, 256>>>();
    k_lift<<<BATCH * 256, 256>>>(x, lw1, lb1, lw2, lb2);

    for (int l = 0; l < NL; ++l) {
        int cur = l & 1;
        k2_hdft<<<BATCH * CW, 256, SMEM_K2>>>();
        k3_mix<<<MH * 8, 256>>>(sp1, sp2, l);
        k4_invh<<<BATCH * CW * 2, 256>>>();
        k5_combine<<<BATCH * HP, 256, SMEM_K5>>>(cur, cw, cb, l, out);
    }
}

// round 17
// speedup vs baseline: 1.2628x; 1.0494x over previous
#include <cuda_runtime.h>
#include <cuda_fp16.h>
#include <math.h>

#define BATCH 8
#define CW    64
#define H0    256
#define W0    256
#define HP    264
#define WP    264
#define MW    32      // kept kx modes
#define MH    64      // kept ky modes (32 top + 32 bottom)
#define NL    4
#define ROWW  8448    // words per (b,h) field row: 32 kp * 264 w

// ---------------- scratch (device globals; no allocation allowed) ----------
// field in pre-interleaved pair layout: word [b][h][kp*264+w] = (ch 2kp, ch 2kp+1) fp16
__device__ __align__(128) unsigned g_hp[2][BATCH*HP*ROWW];  // 2 x 71.4 MB
__device__ __align__(128) unsigned g_x1h[BATCH*CW*HP*MW];   // 17.3 MB packed (re,im)
__device__ __align__(128) float    g_x2r[BATCH*CW*128*32];  // 8.4 MB (split re/im rows)
__device__ __align__(128) unsigned g_y2h[BATCH*CW*MH*MW];   // 4.2 MB packed (re,im)
__device__ __align__(128) __half   g_y1h[BATCH*HP*64*64];   // 17.3 MB [b][h][o][kk]
// fp16 fragment tables (k16)
__device__ __align__(128) uint2 g_fwfh[17*8*32];            // W-DFT B frags
__device__ __align__(128) uint2 g_awfh[4*34*32];            // c2r invW B frags
__device__ __align__(128) uint4 g_fhfh[8*33*32];            // H-DFT A frags
__device__ __align__(128) uint4 g_ghfh[33*8*32];            // invH A frags

__device__ __forceinline__ float gelu_f(float v) {
    return 0.5f * v * (1.0f + erff(v * 0.70710678118654752f));
}

__device__ __forceinline__ unsigned packh(float a, float b) {
    __half2 h = __halves2half2(__float2half_rn(a), __float2half_rn(b));
    return *reinterpret_cast<unsigned*>(&h);
}

// mma.m16n8k16 fp16 in, fp32 accum
__device__ __forceinline__ void mma_f16(float* d, unsigned a0, unsigned a1,
                                        unsigned a2, unsigned a3,
                                        unsigned b0, unsigned b1) {
    asm("mma.sync.aligned.m16n8k16.row.col.f32.f16.f16.f32 "
        "{%0,%1,%2,%3}, {%4,%5,%6,%7}, {%8,%9}, {%0,%1,%2,%3};"
        : "+f"(d[0]), "+f"(d[1]), "+f"(d[2]), "+f"(d[3])
        : "r"(a0), "r"(a1), "r"(a2), "r"(a3), "r"(b0), "r"(b1));
}

#define TWO_PI_D 6.283185307179586476925286766559
#define W_STEP   ((float)(TWO_PI_D / (double)WP))
#define H_STEP   ((float)(TWO_PI_D / (double)HP))

__device__ __forceinline__ float fwB_val(int n, int w) {
    if (w >= WP) return 0.f;
    int kx = n >> 1, p = n & 1;
    int m = (w * kx) % WP;
    float s, c; __sincosf((float)m * W_STEP, &s, &c);
    return p ? -s : c;
}
__device__ __forceinline__ float awB_val(int kk, int w) {
    if (w >= WP) return 0.f;
    int k = kk >> 1;
    float sc = ((k == 0) ? 1.0f : 2.0f) * (float)(1.0 / ((double)HP * (double)WP));
    int m = (k * w) % WP;
    float s, c; __sincosf((float)m * W_STEP, &s, &c);
    return (kk & 1) ? (-sc * s) : (sc * c);
}
__device__ __forceinline__ float fh_val(int jp, int kp) {
    int j = jp >> 1, pj = jp & 1, h = kp >> 1, ph = kp & 1;
    int ky = (j < 32) ? j : j + (HP - MH);
    int m = (h * ky) % HP;
    float s, c; __sincosf((float)m * H_STEP, &s, &c);
    return pj ? (ph ? c : -s) : (ph ? s : c);
}
__device__ __forceinline__ float gh_val(int hpp, int jp) {
    int h = hpp >> 1, ph = hpp & 1, j = jp >> 1, pj = jp & 1;
    int ky = (j < 32) ? j : j + (HP - MH);
    int m = (h * ky) % HP;
    float s, c; __sincosf((float)m * H_STEP, &s, &c);
    return ph ? (pj ? c : s) : (pj ? -s : c);
}

// ---------------- fragment-table init (fp32 trig, 1 item/thread) ----------
__global__ void k_init() {
    int i = blockIdx.x * 256 + threadIdx.x;               // 0..25599
    if (i < 4352) {             // g_fwfh [kt][nt][lane]
        int kt = i >> 8, rem = i & 255;
        int nt = rem >> 5, lane = rem & 31;
        int r = lane >> 2, c = lane & 3;
        int n = nt * 8 + r;
        int w0 = kt * 16 + 2 * c;
        g_fwfh[i] = make_uint2(packh(fwB_val(n, w0),     fwB_val(n, w0 + 1)),
                               packh(fwB_val(n, w0 + 8), fwB_val(n, w0 + 9)));
    } else if (i < 8704) {      // g_awfh [kt][ntg][lane]
        int j = i - 4352;
        int kt = j / (34 * 32), rem = j - kt * (34 * 32);
        int ntg = rem >> 5, lane = rem & 31;
        int r = lane >> 2, c = lane & 3;
        int w = ntg * 8 + r;
        int kk0 = kt * 16 + 2 * c;
        g_awfh[j] = make_uint2(packh(awB_val(kk0, w),     awB_val(kk0 + 1, w)),
                               packh(awB_val(kk0 + 8, w), awB_val(kk0 + 9, w)));
    } else if (i < 17152) {     // g_fhfh [mt][kt][lane]
        int j = i - 8704;
        int mt = j / (33 * 32), rem = j - mt * (33 * 32);
        int kt = rem >> 5, lane = rem & 31;
        int r = lane >> 2, c = lane & 3;
        int row0 = mt * 16 + r, k0 = kt * 16 + 2 * c;
        g_fhfh[j] = make_uint4(
            packh(fh_val(row0, k0),         fh_val(row0, k0 + 1)),
            packh(fh_val(row0 + 8, k0),     fh_val(row0 + 8, k0 + 1)),
            packh(fh_val(row0, k0 + 8),     fh_val(row0, k0 + 9)),
            packh(fh_val(row0 + 8, k0 + 8), fh_val(row0 + 8, k0 + 9)));
    } else {                    // g_ghfh [mt][kt][lane]
        int j = i - 17152;
        int mt = j >> 8, rem = j & 255;
        int kt = rem >> 5, lane = rem & 31;
        int r = lane >> 2, c = lane & 3;
        int row0 = mt * 16 + r, k0 = kt * 16 + 2 * c;
        g_ghfh[j] = make_uint4(
            packh(gh_val(row0, k0),         gh_val(row0, k0 + 1)),
            packh(gh_val(row0 + 8, k0),     gh_val(row0 + 8, k0 + 1)),
            packh(gh_val(row0, k0 + 8),     gh_val(row0, k0 + 9)),
            packh(gh_val(row0 + 8, k0 + 8), gh_val(row0 + 8, k0 + 9)));
    }
}

// Zero x1 pad rows (h >= H0) + g_hp[0] pad h-rows for layer 0
__global__ void k_zero_pad() {
    int blk = blockIdx.x, t = threadIdx.x;
    unsigned* xr = g_x1h + ((size_t)blk * HP + H0) * MW;
    for (int i = t; i < 8 * MW; i += 256) xr[i] = 0u;
    if (blk < 64) {
        int b = blk >> 3, hh = H0 + (blk & 7);
        unsigned* pp = g_hp[0] + (size_t)(b * HP + hh) * ROWW;
        for (int i = t; i < ROWW; i += 256) pp[i] = 0u;
    }
}

// ---------------- lift (+fused W-DFT for layer 0) --------------------------
__global__ __launch_bounds__(256) void k_lift(
        const float* __restrict__ x,
        const float* __restrict__ w1, const float* __restrict__ b1,
        const float* __restrict__ w2, const float* __restrict__ b2) {
    __shared__ float sw1[160], sb1[32], sw2[2048], sb2[64];
    __shared__ unsigned sT[64 * 132 + 8];                // fp16 tile [o][w-pair]
    int t = threadIdx.x;
    if (t < 160) sw1[t] = w1[t];
    if (t < 32)  sb1[t] = b1[t];
    for (int i = t; i < 2048; i += 256) sw2[i] = w2[i];
    if (t < 64)  sb2[t] = b2[t];
    __syncthreads();
    int b = blockIdx.x >> 8, h = blockIdx.x & 255, w = t;
    float in5[5];
#pragma unroll
    for (int c = 0; c < 3; ++c)
        in5[c] = x[(((size_t)b * 3 + c) * H0 + h) * W0 + w];
    in5[3] = (float)h * (1.0f / 255.0f);
    in5[4] = (float)w * (1.0f / 255.0f);
    float mid[32];
#pragma unroll
    for (int o = 0; o < 32; ++o) {
        float s = sb1[o];
#pragma unroll
        for (int i = 0; i < 5; ++i) s = fmaf(sw1[o * 5 + i], in5[i], s);
        mid[o] = gelu_f(s);
    }
    __half* sTh = reinterpret_cast<__half*>(sT);
#pragma unroll 4
    for (int o = 0; o < 64; ++o) {
        float s = sb2[o];
#pragma unroll
        for (int i = 0; i < 32; ++i) s = fmaf(sw2[o * 32 + i], mid[i], s);
        sTh[o * 264 + w] = __float2half_rn(s);
    }
    __half z = __float2half_rn(0.f);
    for (int i = t; i < 64 * 8; i += 256)
        sTh[(i >> 3) * 264 + 256 + (i & 7)] = z;         // pad w 256..263
    if (t < 8) sT[64 * 132 + t] = 0u;
    __syncthreads();
    // interleaved field store (layer-0 g_hp)
    {
        unsigned* hp0 = g_hp[0] + (size_t)(b * HP + h) * ROWW;
        for (int idx = t; idx < 4224; idx += 256) {
            int kp = idx / 132, wp = idx - kp * 132;
            unsigned u0 = sT[(2 * kp) * 132 + wp];
            unsigned u1 = sT[(2 * kp + 1) * 132 + wp];
            *reinterpret_cast<uint2*>(&hp0[kp * 264 + 2 * wp]) =
                make_uint2(__byte_perm(u0, u1, 0x5410), __byte_perm(u0, u1, 0x7632));
        }
    }
    // fused W-DFT (identical math to standalone k1)
    int lane = t & 31, wid = t >> 5;
    int mi = wid & 3, nh = wid >> 2;
    int m0 = mi * 16;
    int c = lane & 3, r = lane >> 2;
    float acc[4][4];
#pragma unroll
    for (int j = 0; j < 4; ++j) {
        acc[j][0] = 0.f; acc[j][1] = 0.f; acc[j][2] = 0.f; acc[j][3] = 0.f;
    }
    int aw0 = (m0 + r) * 132 + c;
    int aw1 = aw0 + 8 * 132;
#pragma unroll 4
    for (int kt = 0; kt < 17; ++kt) {
        unsigned a0 = sT[aw0 + kt * 8];
        unsigned a1 = sT[aw1 + kt * 8];
        unsigned a2 = sT[aw0 + kt * 8 + 4];
        unsigned a3 = sT[aw1 + kt * 8 + 4];
        const uint2* bp = &g_fwfh[(kt * 8 + nh * 4) * 32 + lane];
#pragma unroll
        for (int j = 0; j < 4; ++j) {
            uint2 bb = __ldg(&bp[j * 32]);
            mma_f16(acc[j], a0, a1, a2, a3, bb.x, bb.y);
        }
    }
    size_t rowc = (size_t)b * CW + m0 + r;
#pragma unroll
    for (int j = 0; j < 4; ++j) {
        int kx = (nh * 4 + j) * 4 + c;
        g_x1h[(rowc * HP + h) * MW + kx]       = packh(acc[j][0], acc[j][1]);
        g_x1h[((rowc + 8) * HP + h) * MW + kx] = packh(acc[j][2], acc[j][3]);
    }
}

// ---------------- K2: H-DFT via fp16 mma -----------------------------------
__global__ __launch_bounds__(256, 4) void k2_hdft() {
    extern __shared__ unsigned sBw[];                    // 264*40 words
    int bc = blockIdx.x;
    int t = threadIdx.x;
    const uint4* xp = reinterpret_cast<const uint4*>(g_x1h + (size_t)bc * HP * MW);
    for (int idx = t; idx < HP * 8; idx += 256) {
        int h = idx >> 3, kq = idx & 7;
        *reinterpret_cast<uint4*>(&sBw[h * 40 + kq * 4]) = xp[idx];
    }
    __syncthreads();
    int lane = t & 31, wid = t >> 5;                     // wid = mt
    int c = lane & 3, r = lane >> 2;
    float acc[4][4];
#pragma unroll
    for (int nt = 0; nt < 4; ++nt) {
        acc[nt][0] = 0.f; acc[nt][1] = 0.f; acc[nt][2] = 0.f; acc[nt][3] = 0.f;
    }
#pragma unroll 3
    for (int kt = 0; kt < 33; ++kt) {
        uint4 fa = __ldg(&g_fhfh[(wid * 33 + kt) * 32 + lane]);
        int bw = (kt * 8 + c) * 40 + r;
#pragma unroll
        for (int nt = 0; nt < 4; ++nt) {
            unsigned b0 = sBw[bw + nt * 8];
            unsigned b1 = sBw[bw + 4 * 40 + nt * 8];
            mma_f16(acc[nt], fa.x, fa.y, fa.z, fa.w, b0, b1);
        }
    }
    int row0 = wid * 16 + r, row1 = row0 + 8;
#pragma unroll
    for (int nt = 0; nt < 4; ++nt) {
        int kxa = nt * 8 + 2 * c;
        *reinterpret_cast<float2*>(&g_x2r[((size_t)bc * 128 + row0) * 32 + kxa]) =
            make_float2(acc[nt][0], acc[nt][1]);
        *reinterpret_cast<float2*>(&g_x2r[((size_t)bc * 128 + row1) * 32 + kxa]) =
            make_float2(acc[nt][2], acc[nt][3]);
    }
}

// ---------------- K3: per-mode channel mixing (x2 -> y2h packed fp16) ------
__global__ __launch_bounds__(256) void k3_mix(const float* __restrict__ spw1,
                                              const float* __restrict__ spw2, int l) {
    __shared__ float2 sX[2 * 64 * 32];                   // [b2][i][kx] 32 KB
    int blk = blockIdx.x;
    int jj = blk >> 3, bp = (blk >> 1) & 3, oh = blk & 1;
    int b0 = bp * 2;
    int t = threadIdx.x, kx = t & 31, sub = t >> 5;
    for (int idx = t; idx < 4096; idx += 256) {
        int bi = idx >> 11, rest = idx & 2047;
        int i = rest >> 5, kxl = rest & 31;
        const float* pp = g_x2r + ((size_t)((b0 + bi) * CW + i) * 128 + 2 * jj) * 32;
        sX[idx] = make_float2(pp[kxl], pp[32 + kxl]);
    }
    __syncthreads();
    const float2* wp; int jx;
    if (jj < 32) { wp = (const float2*)spw1; jx = jj; }
    else         { wp = (const float2*)spw2; jx = jj - 32; }
    size_t wbase = (size_t)l * 4194304 + (size_t)jx * 32 + kx;
    int obase = oh * 32 + sub * 4;
    float2 a0[4], a1[4];
#pragma unroll
    for (int q = 0; q < 4; ++q) { a0[q] = make_float2(0.f, 0.f); a1[q] = make_float2(0.f, 0.f); }
#pragma unroll 4
    for (int i = 0; i < 64; ++i) {
        float2 x0 = sX[i * 32 + kx];
        float2 x1 = sX[2048 + i * 32 + kx];
        size_t row = wbase + (size_t)(i * 64 + obase) * 1024;
#pragma unroll
        for (int q = 0; q < 4; ++q) {
            float2 c = __ldg(&wp[row + (size_t)q * 1024]);
            a0[q].x = fmaf(x0.x, c.x, a0[q].x); a0[q].x = fmaf(-x0.y, c.y, a0[q].x);
            a0[q].y = fmaf(x0.x, c.y, a0[q].y); a0[q].y = fmaf( x0.y, c.x, a0[q].y);
            a1[q].x = fmaf(x1.x, c.x, a1[q].x); a1[q].x = fmaf(-x1.y, c.y, a1[q].x);
            a1[q].y = fmaf(x1.x, c.y, a1[q].y); a1[q].y = fmaf( x1.y, c.x, a1[q].y);
        }
    }
#pragma unroll
    for (int q = 0; q < 4; ++q) {
        int o = obase + q;
        g_y2h[(((size_t)b0       * CW + o) * MH + jj) * MW + kx] = packh(a0[q].x, a0[q].y);
        g_y2h[(((size_t)(b0 + 1) * CW + o) * MH + jj) * MW + kx] = packh(a1[q].x, a1[q].y);
    }
}

// ---------------- K4: inverse H-DFT via fp16 mma (mt split over 2 blocks) --
__global__ __launch_bounds__(256) void k4_invh() {
    __shared__ unsigned sBw[64 * 40];
    int blk = blockIdx.x;
    int bo = blk >> 1, half = blk & 1;
    int b = bo >> 6, o = bo & 63;
    int t = threadIdx.x;
    const uint4* yp = reinterpret_cast<const uint4*>(g_y2h + (size_t)bo * MH * MW);
    for (int idx = t; idx < MH * 8; idx += 256) {
        int j = idx >> 3, kq = idx & 7;
        *reinterpret_cast<uint4*>(&sBw[j * 40 + kq * 4]) = yp[idx];
    }
    __syncthreads();
    int lane = t & 31, wid = t >> 5;
    int c = lane & 3, r = lane >> 2;
    int mtEnd = half ? 33 : 16;
    for (int mt = wid + half * 16; mt < mtEnd; mt += 8) {
        float acc[4][4];
#pragma unroll
        for (int nt = 0; nt < 4; ++nt) {
            acc[nt][0] = 0.f; acc[nt][1] = 0.f; acc[nt][2] = 0.f; acc[nt][3] = 0.f;
        }
#pragma unroll
        for (int kt = 0; kt < 8; ++kt) {
            uint4 fa = __ldg(&g_ghfh[(mt * 8 + kt) * 32 + lane]);
            int bw = (kt * 8 + c) * 40 + r;
#pragma unroll
            for (int nt = 0; nt < 4; ++nt) {
                unsigned b0 = sBw[bw + nt * 8];
                unsigned b1 = sBw[bw + 4 * 40 + nt * 8];
                mma_f16(acc[nt], fa.x, fa.y, fa.z, fa.w, b0, b1);
            }
        }
        int h0a = mt * 16 + r, h0b = h0a + 8;
        int ha = h0a >> 1, pa = h0a & 1;
        int hb2 = h0b >> 1, pb = h0b & 1;
        size_t basea = ((size_t)(b * HP + ha) * 64 + o) * 64 + pa;
        size_t baseb = ((size_t)(b * HP + hb2) * 64 + o) * 64 + pb;
#pragma unroll
        for (int nt = 0; nt < 4; ++nt) {
            int kka = 2 * (nt * 8 + 2 * c);
            g_y1h[basea + kka]     = __float2half_rn(acc[nt][0]);
            g_y1h[basea + kka + 2] = __float2half_rn(acc[nt][1]);
            g_y1h[baseb + kka]     = __float2half_rn(acc[nt][2]);
            g_y1h[baseb + kka + 2] = __float2half_rn(acc[nt][3]);
        }
    }
}

// ---------------- K5: fp16 mma GEMM + fused W-DFT + interleaved store ------
// sT tile aliases sBw (all sBw reads complete before epilogue writes sT)
__global__ __launch_bounds__(256, 2)
void k5_combine(int cur, const float* __restrict__ cw,
                const float* __restrict__ cb, int l,
                float* __restrict__ out) {
    extern __shared__ unsigned s_raw_u[];
    unsigned* sAw = s_raw_u;                      // [o][kpair] stride 68 words
    unsigned* sBw = s_raw_u + 64 * 68;            // [kpair][w] stride 264 (+16 slack)
    unsigned* sT  = sBw;                          // ALIAS: out tile [o][w-pair]
    int bh = blockIdx.x;
    int b = bh / HP, h = bh - b * HP;
    bool last = (l == NL - 1);
    if (last && h >= H0) return;
    int t = threadIdx.x;
    // stage B: contiguous memcpy of the pre-interleaved field row
    {
        const uint4* src = reinterpret_cast<const uint4*>(
            g_hp[cur] + (size_t)(b * HP + h) * ROWW);
        uint4* dst = reinterpret_cast<uint4*>(sBw);
        for (int idx = t; idx < ROWW / 4; idx += 256) dst[idx] = src[idx];
        if (t < 16) sBw[32 * 264 + t] = 0u;
    }
    // stage A: conv weights (fp32 src) + spectral coeffs (fp16 src, direct copy)
    {
        const float* cwl = cw + (size_t)l * 4096;
        for (int idx = t; idx < 2048; idx += 256) {
            int o = idx >> 5, ip = idx & 31;
            sAw[o * 68 + ip] = packh(cwl[o * 64 + 2 * ip], cwl[o * 64 + 2 * ip + 1]);
        }
        const unsigned* yb = reinterpret_cast<const unsigned*>(
            g_y1h + (size_t)(b * HP + h) * 4096);
        for (int idx = t; idx < 2048; idx += 256) {
            int o = idx >> 5, kp = idx & 31;
            sAw[o * 68 + 32 + kp] = yb[o * 32 + kp];
        }
    }
    __syncthreads();
    int lane = t & 31, wid = t >> 5;
    int mi = wid & 3, nh = wid >> 2;
    int m0 = mi * 16;
    int c = lane & 3, r = lane >> 2;
    int ntBeg = nh * 17;
    float acc[17][4];
#pragma unroll
    for (int j = 0; j < 17; ++j) {
        acc[j][0] = 0.f; acc[j][1] = 0.f; acc[j][2] = 0.f; acc[j][3] = 0.f;
    }
    int aw0 = (m0 + r) * 68 + c;
    int aw1 = aw0 + 8 * 68;
    // conv half (kt 0..3): B from smem
#pragma unroll
    for (int kt = 0; kt < 4; ++kt) {
        unsigned a0 = sAw[aw0 + kt * 8];
        unsigned a1 = sAw[aw1 + kt * 8];
        unsigned a2 = sAw[aw0 + kt * 8 + 4];
        unsigned a3 = sAw[aw1 + kt * 8 + 4];
        int bw = (kt * 8 + c) * 264 + r + ntBeg * 8;
#pragma unroll
        for (int j = 0; j < 17; ++j) {
            unsigned b0 = sBw[bw + j * 8];
            unsigned b1 = sBw[bw + 4 * 264 + j * 8];
            mma_f16(acc[j], a0, a1, a2, a3, b0, b1);
        }
    }
    // spectral half (kt 4..7): B frags pre-swizzled in g_awfh
#pragma unroll
    for (int kt = 4; kt < 8; ++kt) {
        unsigned a0 = sAw[aw0 + kt * 8];
        unsigned a1 = sAw[aw1 + kt * 8];
        unsigned a2 = sAw[aw0 + kt * 8 + 4];
        unsigned a3 = sAw[aw1 + kt * 8 + 4];
        const uint2* bp = &g_awfh[((kt - 4) * 34 + ntBeg) * 32 + lane];
#pragma unroll
        for (int j = 0; j < 17; ++j) {
            uint2 bb = __ldg(&bp[j * 32]);
            mma_f16(acc[j], a0, a1, a2, a3, bb.x, bb.y);
        }
    }
    // all sBw reads done; sT may now overwrite it
    __syncthreads();
    int o0 = m0 + r, o1 = o0 + 8;
    float bias0 = __ldg(&cb[l * 64 + o0]);
    float bias1 = __ldg(&cb[l * 64 + o1]);
#pragma unroll
    for (int j = 0; j < 17; ++j) {
        if (nh && j == 16) continue;
        int n0 = (ntBeg + j) * 8;
        int wcol = n0 + 2 * c;
        float2 p0 = make_float2(acc[j][0] + bias0, acc[j][1] + bias0);
        float2 p1 = make_float2(acc[j][2] + bias1, acc[j][3] + bias1);
        if (!last) {
            p0.x = gelu_f(p0.x); p0.y = gelu_f(p0.y);
            p1.x = gelu_f(p1.x); p1.y = gelu_f(p1.y);
            int wword = 4 * (ntBeg + j) + c;
            sT[o0 * 132 + wword] = packh(p0.x, p0.y);
            sT[o1 * 132 + wword] = packh(p1.x, p1.y);
        } else if (n0 < W0) {
            *reinterpret_cast<float2*>(
                &out[(((size_t)b * CW + o0) * H0 + h) * W0 + wcol]) = p0;
            *reinterpret_cast<float2*>(
                &out[(((size_t)b * CW + o1) * H0 + h) * W0 + wcol]) = p1;
        }
    }
    if (!last) {
        if (t < 8) sT[64 * 132 + t] = 0u;
        __syncthreads();
        // interleaved field store (next layer's B)
        {
            unsigned* hpn = g_hp[cur ^ 1] + (size_t)(b * HP + h) * ROWW;
            for (int idx = t; idx < 4224; idx += 256) {
                int kp = idx / 132, wp = idx - kp * 132;
                unsigned u0 = sT[(2 * kp) * 132 + wp];
                unsigned u1 = sT[(2 * kp + 1) * 132 + wp];
                *reinterpret_cast<uint2*>(&hpn[kp * 264 + 2 * wp]) =
                    make_uint2(__byte_perm(u0, u1, 0x5410), __byte_perm(u0, u1, 0x7632));
            }
        }
        // fused W-DFT of the freshly computed field row-block (next layer's x1)
        float fac[4][4];
#pragma unroll
        for (int j = 0; j < 4; ++j) {
            fac[j][0] = 0.f; fac[j][1] = 0.f; fac[j][2] = 0.f; fac[j][3] = 0.f;
        }
        int fa0 = (m0 + r) * 132 + c;
        int fa1 = fa0 + 8 * 132;
#pragma unroll 4
        for (int kt = 0; kt < 17; ++kt) {
            unsigned a0 = sT[fa0 + kt * 8];
            unsigned a1 = sT[fa1 + kt * 8];
            unsigned a2 = sT[fa0 + kt * 8 + 4];
            unsigned a3 = sT[fa1 + kt * 8 + 4];
            const uint2* bp = &g_fwfh[(kt * 8 + nh * 4) * 32 + lane];
#pragma unroll
            for (int j = 0; j < 4; ++j) {
                uint2 bb = __ldg(&bp[j * 32]);
                mma_f16(fac[j], a0, a1, a2, a3, bb.x, bb.y);
            }
        }
        size_t rowc = (size_t)b * CW + m0 + r;
#pragma unroll
        for (int j = 0; j < 4; ++j) {
            int kx = (nh * 4 + j) * 4 + c;
            g_x1h[(rowc * HP + h) * MW + kx]       = packh(fac[j][0], fac[j][1]);
            g_x1h[((rowc + 8) * HP + h) * MW + kx] = packh(fac[j][2], fac[j][3]);
        }
    }
}

// ---------------- launch ---------------------------------------------------
extern "C" void kernel_launch(void* const* d_in, const int* in_sizes, int n_in,
                              void* d_out, int out_size) {
    const float* x   = (const float*)d_in[0];
    const float* lw1 = (const float*)d_in[1];
    const float* lb1 = (const float*)d_in[2];
    const float* lw2 = (const float*)d_in[3];
    const float* lb2 = (const float*)d_in[4];
    const float* cw  = (const float*)d_in[5];
    const float* cb  = (const float*)d_in[6];
    const float* sp1 = (const float*)d_in[7];
    const float* sp2 = (const float*)d_in[8];
    float* out = (float*)d_out;

    const int SMEM_K2 = 264 * 40 * 4;                      // 42240
    const int SMEM_K5 = (64 * 68 + 32 * 264 + 16) * 4;     // 51264 (sT aliases sBw)

    cudaFuncSetAttribute(k2_hdft,    cudaFuncAttributeMaxDynamicSharedMemorySize, SMEM_K2);
    cudaFuncSetAttribute(k5_combine, cudaFuncAttributeMaxDynamicSharedMemorySize, SMEM_K5);

    k_init<<<100, 256>>>();
    k_zero_pad<<<BATCH * CW, 256>>>();
    k_lift<<<BATCH * 256, 256>>>(x, lw1, lb1, lw2, lb2);

    for (int l = 0; l < NL; ++l) {
        int cur = l & 1;
        k2_hdft<<<BATCH * CW, 256, SMEM_K2>>>();
        k3_mix<<<MH * 8, 256>>>(sp1, sp2, l);
        k4_invh<<<BATCH * CW * 2, 256>>>();
        k5_combine<<<BATCH * HP, 256, SMEM_K5>>>(cur, cw, cb, l, out);
    }
}